// round 1
// baseline (speedup 1.0000x reference)
#include <cuda_runtime.h>
#include <math.h>

#define Z 2
#define NPT 256          // N points
#define CH 16
#define HEADS 2
#define NB 10
#define HD 100
#define NBV 3
#define ATILE 64

// ---------------- scratch (device globals; no allocation allowed) ----------------
__device__ float g_q[HEADS * Z * NPT * CH];                  // 16K
__device__ float g_WfF[HEADS * Z * NPT * HD * CH];           // 1.64M floats
__device__ float g_VfF[HEADS * Z * NPT * HD * CH];           // 1.64M floats
__device__ float g_CfF[Z * NPT * HD * CH];                   // 0.82M floats
__device__ float g_scores[HEADS * Z * NPT * NPT];            // 262K floats
__device__ float g_valt[HEADS * Z * NPT * NPT * CH];         // 4.19M floats (16.8MB)
__device__ float g_attnout[Z * NPT * CH];                    // 8K floats

__device__ __forceinline__ float swishf(float x) {
    return x / (1.0f + __expf(-x));
}

// ---------------- Kernel A: per-(z,b) projections: q, WfF, VfF ----------------
__global__ void proj_kernel(const float* __restrict__ features,
                            const float* __restrict__ Wq,
                            const float* __restrict__ Kf,
                            const float* __restrict__ Vf) {
    const int bid = blockIdx.x;
    const int z = bid / NPT, b = bid % NPT;
    const int tid = threadIdx.x;
    __shared__ float fs[CH];
    if (tid < CH) fs[tid] = features[(z * NPT + b) * CH + tid];
    __syncthreads();

    if (tid < HEADS * CH) {
        int h = tid >> 4, o = tid & 15;
        float acc = 0.f;
#pragma unroll
        for (int i = 0; i < CH; i++) acc += fs[i] * Wq[(h * CH + o) * CH + i];
        g_q[((h * Z + z) * NPT + b) * CH + o] = acc;
    }
    for (int e = tid; e < HEADS * HD * CH; e += blockDim.x) {
        int h = e / (HD * CH);
        int r = e - h * (HD * CH);
        int m = r >> 4, i = r & 15;
        const float* kp = Kf + (h * HD + m) * (CH * CH) + i * CH;
        const float* vp = Vf + (h * HD + m) * (CH * CH) + i * CH;
        float accK = 0.f, accV = 0.f;
#pragma unroll
        for (int j = 0; j < CH; j++) { accK += kp[j] * fs[j]; accV += vp[j] * fs[j]; }
        int o = ((h * Z + z) * NPT + b) * (HD * CH) + r;
        g_WfF[o] = accK;
        g_VfF[o] = accV;
    }
}

// ---------------- Kernel P: pair kernel (per head): scores + val_t ----------------
// grid: (NPT b, NPT/ATILE a-tiles, Z*HEADS), 256 threads
#define P_SMEM_FLOATS 28196
__global__ __launch_bounds__(256, 2) void pair_kernel(const float* __restrict__ xyz,
                                                      const float* __restrict__ K0g,
                                                      const float* __restrict__ K1g,
                                                      const float* __restrict__ V0g) {
    extern __shared__ float sm[];
    float* s_k0  = sm;                // 1000
    float* s_k1  = sm + 1000;         // 10000
    float* s_v0  = sm + 11000;        // 300
    float* s_wff = sm + 11300;        // 1600
    float* s_vff = sm + 12900;        // 1600
    float* s_bas = sm + 14500;        // 640
    float* s_bas3= sm + 15140;        // 192
    float* s_d   = sm + 15332;        // 64
    float* s_h1  = sm + 15396;        // 6400
    float* s_h2  = sm + 21796;        // 6400

    const int tid = threadIdx.x;
    const int b = blockIdx.x;
    const int a0 = blockIdx.y * ATILE;
    const int z = blockIdx.z >> 1;
    const int h = blockIdx.z & 1;

    for (int i = tid; i < NB * HD; i += 256) s_k0[i] = K0g[h * NB * HD + i];
    for (int i = tid; i < HD * HD; i += 256) s_k1[i] = K1g[h * HD * HD + i];
    for (int i = tid; i < NBV * HD; i += 256) s_v0[i] = V0g[h * NBV * HD + i];
    {
        const int base = ((h * Z + z) * NPT + b) * (HD * CH);
        for (int i = tid; i < HD * CH; i += 256) {
            s_wff[i] = g_WfF[base + i];
            s_vff[i] = g_VfF[base + i];
        }
    }
    if (tid < ATILE) {
        int a = a0 + tid;
        float bx = xyz[(z * NPT + b) * 3 + 0];
        float by = xyz[(z * NPT + b) * 3 + 1];
        float bz = xyz[(z * NPT + b) * 3 + 2];
        float dx = bx - xyz[(z * NPT + a) * 3 + 0];
        float dy = by - xyz[(z * NPT + a) * 3 + 1];
        float dz = bz - xyz[(z * NPT + a) * 3 + 2];
        s_d[tid] = sqrtf(dx * dx + dy * dy + dz * dz + 1e-12f);
    }
    __syncthreads();

    // cosine bases
    const float STEP10 = 5.0f / 9.0f;
    const float INV10 = 9.0f / 5.0f;
    for (int e = tid; e < ATILE * NB; e += 256) {
        int p = e / NB, n = e - p * NB;
        float diff = (s_d[p] - n * STEP10) * INV10;
        s_bas[e] = (fabsf(diff) < 1.0f) ? cospif(0.5f * diff) : 0.0f;
    }
    for (int e = tid; e < ATILE * NBV; e += 256) {
        int p = e / NBV, n = e - p * NBV;
        float diff = (s_d[p] - n * 2.5f) * 0.4f;
        s_bas3[e] = (fabsf(diff) < 1.0f) ? cospif(0.5f * diff) : 0.0f;
    }
    __syncthreads();

    // H1 = swish(basis @ K0)
    for (int e = tid; e < ATILE * HD; e += 256) {
        int p = e / HD, m = e - p * HD;
        float acc = 0.f;
#pragma unroll
        for (int n = 0; n < NB; n++) acc += s_bas[p * NB + n] * s_k0[n * HD + m];
        s_h1[e] = swishf(acc);
    }
    __syncthreads();

    // H2 = swish(H1 @ K1)  -- register tiled: 4 pairs x up to 7 m per thread
    {
        const int ty = tid >> 4, tx = tid & 15;
        float acc[4][7];
#pragma unroll
        for (int r = 0; r < 4; r++)
#pragma unroll
            for (int k = 0; k < 7; k++) acc[r][k] = 0.f;
        for (int n = 0; n < HD; n++) {
            float h1v[4];
#pragma unroll
            for (int r = 0; r < 4; r++) h1v[r] = s_h1[(ty * 4 + r) * HD + n];
#pragma unroll
            for (int k = 0; k < 6; k++) {
                float kv = s_k1[n * HD + tx + 16 * k];
#pragma unroll
                for (int r = 0; r < 4; r++) acc[r][k] += h1v[r] * kv;
            }
            if (tx < 4) {
                float kv = s_k1[n * HD + tx + 96];
#pragma unroll
                for (int r = 0; r < 4; r++) acc[r][6] += h1v[r] * kv;
            }
        }
#pragma unroll
        for (int r = 0; r < 4; r++)
#pragma unroll
            for (int k = 0; k < 6; k++)
                s_h2[(ty * 4 + r) * HD + tx + 16 * k] = swishf(acc[r][k]);
        if (tx < 4)
#pragma unroll
            for (int r = 0; r < 4; r++)
                s_h2[(ty * 4 + r) * HD + tx + 96] = swishf(acc[r][6]);
    }
    __syncthreads();

    // key_t = H2 @ WfF[b], score = dot(key_t, q[a]) / 16
    {
        const int p = tid >> 2, q4 = tid & 3, ig = q4 * 4;
        float ax = 0.f, ay = 0.f, az = 0.f, aw = 0.f;
        for (int m = 0; m < HD; m++) {
            float hv = s_h2[p * HD + m];
            float4 w = *(const float4*)(s_wff + m * CH + ig);
            ax += hv * w.x; ay += hv * w.y; az += hv * w.z; aw += hv * w.w;
        }
        const int a = a0 + p;
        const float* qp = g_q + ((h * Z + z) * NPT + a) * CH + ig;
        float part = ax * qp[0] + ay * qp[1] + az * qp[2] + aw * qp[3];
        part += __shfl_xor_sync(0xffffffffu, part, 1);
        part += __shfl_xor_sync(0xffffffffu, part, 2);
        if (q4 == 0)
            g_scores[((h * Z + z) * NPT + a) * NPT + b] = part * (1.0f / CH);
    }

    // Hv = swish(basis3 @ V0) (reuse s_h1)
    for (int e = tid; e < ATILE * HD; e += 256) {
        int p = e / HD, m = e - p * HD;
        float acc = 0.f;
#pragma unroll
        for (int n = 0; n < NBV; n++) acc += s_bas3[p * NBV + n] * s_v0[n * HD + m];
        s_h1[e] = swishf(acc);
    }
    __syncthreads();

    // val_t = Hv @ VfF[b]
    {
        const int p = tid >> 2, q4 = tid & 3, ig = q4 * 4;
        float4 a4 = make_float4(0.f, 0.f, 0.f, 0.f);
        for (int m = 0; m < HD; m++) {
            float hv = s_h1[p * HD + m];
            float4 w = *(const float4*)(s_vff + m * CH + ig);
            a4.x += hv * w.x; a4.y += hv * w.y; a4.z += hv * w.z; a4.w += hv * w.w;
        }
        const int a = a0 + p;
        float4* op = (float4*)(g_valt + ((size_t)((h * Z + z) * NPT + a) * NPT + b) * CH + ig);
        *op = a4;
    }
}

// ---------------- Kernel S: softmax over b + weighted val_t sum ----------------
__global__ void softmax_kernel() {
    const int bid = blockIdx.x;
    const int z = bid / NPT, a = bid % NPT;
    const int tid = threadIdx.x;     // = b
    __shared__ float red[256];
    __shared__ float vr[256 * CH];

    float accv[CH];
#pragma unroll
    for (int i = 0; i < CH; i++) accv[i] = 0.f;

    for (int h = 0; h < HEADS; h++) {
        float sc = g_scores[((h * Z + z) * NPT + a) * NPT + tid];
        red[tid] = sc; __syncthreads();
        for (int s = 128; s > 0; s >>= 1) {
            if (tid < s) red[tid] = fmaxf(red[tid], red[tid + s]);
            __syncthreads();
        }
        float mx = red[0]; __syncthreads();
        float e = __expf(sc - mx);
        red[tid] = e; __syncthreads();
        for (int s = 128; s > 0; s >>= 1) {
            if (tid < s) red[tid] += red[tid + s];
            __syncthreads();
        }
        float p = e / red[0]; __syncthreads();

        const float4* vp = (const float4*)(g_valt +
            ((size_t)((h * Z + z) * NPT + a) * NPT + tid) * CH);
#pragma unroll
        for (int k = 0; k < 4; k++) {
            float4 v = vp[k];
            accv[k * 4 + 0] += p * v.x;
            accv[k * 4 + 1] += p * v.y;
            accv[k * 4 + 2] += p * v.z;
            accv[k * 4 + 3] += p * v.w;
        }
    }
#pragma unroll
    for (int i = 0; i < CH; i++) vr[tid * CH + i] = accv[i];
    __syncthreads();
    for (int s = 128; s > 0; s >>= 1) {
        if (tid < s)
#pragma unroll
            for (int i = 0; i < CH; i++) vr[tid * CH + i] += vr[(tid + s) * CH + i];
        __syncthreads();
    }
    if (tid < CH) g_attnout[(z * NPT + a) * CH + tid] = vr[tid];
}

// ---------------- Kernel C1: CfF projection of attention output ----------------
__global__ void cff_kernel(const float* __restrict__ Cf) {
    const int bid = blockIdx.x;
    const int z = bid / NPT, b = bid % NPT;
    const int tid = threadIdx.x;
    __shared__ float ao[CH];
    if (tid < CH) ao[tid] = g_attnout[(z * NPT + b) * CH + tid];
    __syncthreads();
    for (int e = tid; e < HD * CH; e += blockDim.x) {
        int m = e >> 4, i = e & 15;
        const float* cp = Cf + m * (CH * CH) + i * CH;
        float acc = 0.f;
#pragma unroll
        for (int j = 0; j < CH; j++) acc += cp[j] * ao[j];
        g_CfF[(z * NPT + b) * (HD * CH) + e] = acc;
    }
}

// ---------------- Kernel C2: final conv pairs, accumulate into out ----------------
#define C_SMEM_FLOATS 26104
__global__ __launch_bounds__(256, 2) void conv_kernel(const float* __restrict__ xyz,
                                                      const float* __restrict__ C0g,
                                                      const float* __restrict__ C1g,
                                                      float* __restrict__ out) {
    extern __shared__ float sm[];
    float* s_c0  = sm;                // 1000
    float* s_c1  = sm + 1000;         // 10000
    float* s_cff = sm + 11000;        // 1600
    float* s_bas = sm + 12600;        // 640
    float* s_d   = sm + 13240;        // 64
    float* s_h1  = sm + 13304;        // 6400
    float* s_h2  = sm + 19704;        // 6400

    const int tid = threadIdx.x;
    const int b = blockIdx.x;
    const int a0 = blockIdx.y * ATILE;
    const int z = blockIdx.z;

    for (int i = tid; i < NB * HD; i += 256) s_c0[i] = C0g[i];
    for (int i = tid; i < HD * HD; i += 256) s_c1[i] = C1g[i];
    {
        const int base = (z * NPT + b) * (HD * CH);
        for (int i = tid; i < HD * CH; i += 256) s_cff[i] = g_CfF[base + i];
    }
    if (tid < ATILE) {
        int a = a0 + tid;
        float bx = xyz[(z * NPT + b) * 3 + 0];
        float by = xyz[(z * NPT + b) * 3 + 1];
        float bz = xyz[(z * NPT + b) * 3 + 2];
        float dx = bx - xyz[(z * NPT + a) * 3 + 0];
        float dy = by - xyz[(z * NPT + a) * 3 + 1];
        float dz = bz - xyz[(z * NPT + a) * 3 + 2];
        s_d[tid] = sqrtf(dx * dx + dy * dy + dz * dz + 1e-12f);
    }
    __syncthreads();

    const float STEP10 = 5.0f / 9.0f;
    const float INV10 = 9.0f / 5.0f;
    for (int e = tid; e < ATILE * NB; e += 256) {
        int p = e / NB, n = e - p * NB;
        float diff = (s_d[p] - n * STEP10) * INV10;
        s_bas[e] = (fabsf(diff) < 1.0f) ? cospif(0.5f * diff) : 0.0f;
    }
    __syncthreads();

    for (int e = tid; e < ATILE * HD; e += 256) {
        int p = e / HD, m = e - p * HD;
        float acc = 0.f;
#pragma unroll
        for (int n = 0; n < NB; n++) acc += s_bas[p * NB + n] * s_c0[n * HD + m];
        s_h1[e] = swishf(acc);
    }
    __syncthreads();

    {
        const int ty = tid >> 4, tx = tid & 15;
        float acc[4][7];
#pragma unroll
        for (int r = 0; r < 4; r++)
#pragma unroll
            for (int k = 0; k < 7; k++) acc[r][k] = 0.f;
        for (int n = 0; n < HD; n++) {
            float h1v[4];
#pragma unroll
            for (int r = 0; r < 4; r++) h1v[r] = s_h1[(ty * 4 + r) * HD + n];
#pragma unroll
            for (int k = 0; k < 6; k++) {
                float kv = s_c1[n * HD + tx + 16 * k];
#pragma unroll
                for (int r = 0; r < 4; r++) acc[r][k] += h1v[r] * kv;
            }
            if (tx < 4) {
                float kv = s_c1[n * HD + tx + 96];
#pragma unroll
                for (int r = 0; r < 4; r++) acc[r][6] += h1v[r] * kv;
            }
        }
#pragma unroll
        for (int r = 0; r < 4; r++)
#pragma unroll
            for (int k = 0; k < 6; k++)
                s_h2[(ty * 4 + r) * HD + tx + 16 * k] = swishf(acc[r][k]);
        if (tx < 4)
#pragma unroll
            for (int r = 0; r < 4; r++)
                s_h2[(ty * 4 + r) * HD + tx + 96] = swishf(acc[r][6]);
    }
    __syncthreads();

    {
        const int p = tid >> 2, q4 = tid & 3, ig = q4 * 4;
        float4 a4 = make_float4(0.f, 0.f, 0.f, 0.f);
        for (int m = 0; m < HD; m++) {
            float hv = s_h2[p * HD + m];
            float4 w = *(const float4*)(s_cff + m * CH + ig);
            a4.x += hv * w.x; a4.y += hv * w.y; a4.z += hv * w.z; a4.w += hv * w.w;
        }
        const int a = a0 + p;
        float* op = out + (z * NPT + a) * CH + ig;
        atomicAdd(op + 0, a4.x);
        atomicAdd(op + 1, a4.y);
        atomicAdd(op + 2, a4.z);
        atomicAdd(op + 3, a4.w);
    }
}

// ---------------- launch ----------------
extern "C" void kernel_launch(void* const* d_in, const int* in_sizes, int n_in,
                              void* d_out, int out_size) {
    const float* features = (const float*)d_in[0];
    const float* xyz = (const float*)d_in[1];
    const float* Wq = (const float*)d_in[2];
    const float* K0 = (const float*)d_in[3];
    const float* K1 = (const float*)d_in[4];
    const float* Kf = (const float*)d_in[5];
    const float* V0 = (const float*)d_in[6];
    const float* Vf = (const float*)d_in[7];
    const float* C0 = (const float*)d_in[8];
    const float* C1 = (const float*)d_in[9];
    const float* Cf = (const float*)d_in[10];
    float* out = (float*)d_out;

    cudaFuncSetAttribute(pair_kernel, cudaFuncAttributeMaxDynamicSharedMemorySize,
                         P_SMEM_FLOATS * (int)sizeof(float));
    cudaFuncSetAttribute(conv_kernel, cudaFuncAttributeMaxDynamicSharedMemorySize,
                         C_SMEM_FLOATS * (int)sizeof(float));

    cudaMemsetAsync(d_out, 0, (size_t)out_size * sizeof(float));

    proj_kernel<<<Z * NPT, 256>>>(features, Wq, Kf, Vf);
    pair_kernel<<<dim3(NPT, NPT / ATILE, Z * HEADS), 256,
                  P_SMEM_FLOATS * sizeof(float)>>>(xyz, K0, K1, V0);
    softmax_kernel<<<Z * NPT, 256>>>();
    cff_kernel<<<Z * NPT, 128>>>(Cf);
    conv_kernel<<<dim3(NPT, NPT / ATILE, Z), 256,
                  C_SMEM_FLOATS * sizeof(float)>>>(xyz, C0, C1, out);
}

// round 2
// speedup vs baseline: 1.3449x; 1.3449x over previous
#include <cuda_runtime.h>
#include <math.h>

#define Z 2
#define NPT 256
#define CH 16
#define HEADS 2
#define NB 10
#define HD 100
#define NBV 3
#define ATILE 64

typedef unsigned long long u64t;

// ---------------- scratch ----------------
__device__ float g_q[HEADS * Z * NPT * CH];
__device__ float g_WfF[HEADS * Z * NPT * HD * CH];
__device__ float g_VfF[HEADS * Z * NPT * HD * CH];
__device__ float g_CfF[Z * NPT * HD * CH];
__device__ float g_scores[HEADS * Z * NPT * NPT];
__device__ float g_valt[HEADS * Z * NPT * NPT * CH];
__device__ float g_attnout[Z * NPT * CH];

__device__ __forceinline__ float swishf(float x) {
    return x / (1.0f + __expf(-x));
}
__device__ __forceinline__ u64t bc2(float x) {
    u64t r;
    asm("mov.b64 %0, {%1, %1};" : "=l"(r) : "f"(x));
    return r;
}
__device__ __forceinline__ void fma2(u64t& d, u64t a, u64t b) {
    asm("fma.rn.f32x2 %0, %1, %2, %0;" : "+l"(d) : "l"(a), "l"(b));
}
__device__ __forceinline__ float2 up2(u64t v) {
    float2 f;
    asm("mov.b64 {%0, %1}, %2;" : "=f"(f.x), "=f"(f.y) : "l"(v));
    return f;
}

// ---------------- Kernel A: projections q, WfF, VfF (8 points / block) ----------------
__global__ __launch_bounds__(256) void proj_kernel(const float* __restrict__ features,
                                                   const float* __restrict__ Wq,
                                                   const float* __restrict__ Kf,
                                                   const float* __restrict__ Vf) {
    const int z = blockIdx.x >> 5;
    const int b0 = (blockIdx.x & 31) * 8;
    const int tid = threadIdx.x;
    __shared__ float fs[8 * CH];
    if (tid < 8 * CH) fs[tid] = features[(z * NPT + b0) * CH + tid];
    __syncthreads();

    // q: 8 b * 2 heads * 16 outs = 256
    {
        const int bl = tid >> 5, r = tid & 31, h = r >> 4, o = r & 15;
        float acc = 0.f;
#pragma unroll
        for (int i = 0; i < CH; i++) acc += fs[bl * CH + i] * Wq[(h * CH + o) * CH + i];
        g_q[((h * Z + z) * NPT + b0 + bl) * CH + o] = acc;
    }

    for (int e = tid; e < HEADS * HD * CH; e += 256) {
        const int h = e / (HD * CH);
        const int r = e - h * (HD * CH);
        const int m = r >> 4, i = r & 15;
        float4 k0 = *(const float4*)(Kf + (h * HD + m) * (CH * CH) + i * CH);
        float4 k1 = *(const float4*)(Kf + (h * HD + m) * (CH * CH) + i * CH + 4);
        float4 k2 = *(const float4*)(Kf + (h * HD + m) * (CH * CH) + i * CH + 8);
        float4 k3 = *(const float4*)(Kf + (h * HD + m) * (CH * CH) + i * CH + 12);
        float4 v0 = *(const float4*)(Vf + (h * HD + m) * (CH * CH) + i * CH);
        float4 v1 = *(const float4*)(Vf + (h * HD + m) * (CH * CH) + i * CH + 4);
        float4 v2 = *(const float4*)(Vf + (h * HD + m) * (CH * CH) + i * CH + 8);
        float4 v3 = *(const float4*)(Vf + (h * HD + m) * (CH * CH) + i * CH + 12);
#pragma unroll
        for (int bl = 0; bl < 8; bl++) {
            const float* f = fs + bl * CH;
            float aK = k0.x*f[0]+k0.y*f[1]+k0.z*f[2]+k0.w*f[3]
                     + k1.x*f[4]+k1.y*f[5]+k1.z*f[6]+k1.w*f[7]
                     + k2.x*f[8]+k2.y*f[9]+k2.z*f[10]+k2.w*f[11]
                     + k3.x*f[12]+k3.y*f[13]+k3.z*f[14]+k3.w*f[15];
            float aV = v0.x*f[0]+v0.y*f[1]+v0.z*f[2]+v0.w*f[3]
                     + v1.x*f[4]+v1.y*f[5]+v1.z*f[6]+v1.w*f[7]
                     + v2.x*f[8]+v2.y*f[9]+v2.z*f[10]+v2.w*f[11]
                     + v3.x*f[12]+v3.y*f[13]+v3.z*f[14]+v3.w*f[15];
            int o = ((h * Z + z) * NPT + b0 + bl) * (HD * CH) + r;
            g_WfF[o] = aK;
            g_VfF[o] = aV;
        }
    }
}

// ---------------- Kernel P: pair kernel ----------------
#define P_SMEM_FLOATS 28196
__global__ __launch_bounds__(256, 2) void pair_kernel(const float* __restrict__ xyz,
                                                      const float* __restrict__ K0g,
                                                      const float* __restrict__ K1g,
                                                      const float* __restrict__ V0g) {
    extern __shared__ float sm[];
    float* s_k0  = sm;                // 1000
    float* s_k1  = sm + 1000;         // 10000
    float* s_v0  = sm + 11000;        // 300
    float* s_wff = sm + 11300;        // 1600
    float* s_vff = sm + 12900;        // 1600
    float* s_bas = sm + 14500;        // 640
    float* s_bas3= sm + 15140;        // 192
    float* s_d   = sm + 15332;        // 64
    float* s_h1t = sm + 15396;        // 6400  [m][p] transposed
    float* s_h2  = sm + 21796;        // 6400  [p][m]

    const int tid = threadIdx.x;
    const int b = blockIdx.x;
    const int a0 = blockIdx.y * ATILE;
    const int z = blockIdx.z >> 1;
    const int h = blockIdx.z & 1;

    for (int i = tid; i < NB * HD; i += 256) s_k0[i] = K0g[h * NB * HD + i];
    for (int i = tid; i < HD * HD; i += 256) s_k1[i] = K1g[h * HD * HD + i];
    for (int i = tid; i < NBV * HD; i += 256) s_v0[i] = V0g[h * NBV * HD + i];
    {
        const int base = ((h * Z + z) * NPT + b) * (HD * CH);
        for (int i = tid; i < HD * CH; i += 256) {
            s_wff[i] = g_WfF[base + i];
            s_vff[i] = g_VfF[base + i];
        }
    }
    if (tid < ATILE) {
        int a = a0 + tid;
        float bx = xyz[(z * NPT + b) * 3 + 0];
        float by = xyz[(z * NPT + b) * 3 + 1];
        float bz = xyz[(z * NPT + b) * 3 + 2];
        float dx = bx - xyz[(z * NPT + a) * 3 + 0];
        float dy = by - xyz[(z * NPT + a) * 3 + 1];
        float dz = bz - xyz[(z * NPT + a) * 3 + 2];
        s_d[tid] = sqrtf(dx * dx + dy * dy + dz * dz + 1e-12f);
    }
    __syncthreads();

    const float STEP10 = 5.0f / 9.0f;
    const float INV10 = 9.0f / 5.0f;
    for (int e = tid; e < ATILE * NB; e += 256) {
        int p = e / NB, n = e - p * NB;
        float diff = (s_d[p] - n * STEP10) * INV10;
        s_bas[e] = (fabsf(diff) < 1.0f) ? cospif(0.5f * diff) : 0.0f;
    }
    for (int e = tid; e < ATILE * NBV; e += 256) {
        int p = e / NBV, n = e - p * NBV;
        float diff = (s_d[p] - n * 2.5f) * 0.4f;
        s_bas3[e] = (fabsf(diff) < 1.0f) ? cospif(0.5f * diff) : 0.0f;
    }
    __syncthreads();

    // H1 = swish(basis @ K0) -> transposed [m][p]
    for (int e = tid; e < ATILE * HD; e += 256) {
        int m = e >> 6, p = e & 63;
        float acc = 0.f;
#pragma unroll
        for (int n = 0; n < NB; n++) acc += s_bas[p * NB + n] * s_k0[n * HD + m];
        s_h1t[e] = swishf(acc);
    }
    __syncthreads();

    // H2 = swish(H1 @ K1): f32x2, thread = (ty: 4 rows, tx: 7 cols)
    {
        const int ty = tid >> 4, tx = tid & 15;
        u64t a01[7], a23[7];
#pragma unroll
        for (int k = 0; k < 7; k++) { a01[k] = 0ull; a23[k] = 0ull; }
        const bool tail = (tx < 4);
        for (int n = 0; n < HD; n++) {
            ulonglong2 hv = *(const ulonglong2*)(s_h1t + n * 64 + ty * 4);
#pragma unroll
            for (int k = 0; k < 6; k++) {
                u64t kk = bc2(s_k1[n * HD + tx + 16 * k]);
                fma2(a01[k], hv.x, kk);
                fma2(a23[k], hv.y, kk);
            }
            if (tail) {
                u64t kk = bc2(s_k1[n * HD + 96 + tx]);
                fma2(a01[6], hv.x, kk);
                fma2(a23[6], hv.y, kk);
            }
        }
#pragma unroll
        for (int k = 0; k < 6; k++) {
            float2 r01 = up2(a01[k]), r23 = up2(a23[k]);
            int c = tx + 16 * k;
            s_h2[(ty * 4 + 0) * HD + c] = swishf(r01.x);
            s_h2[(ty * 4 + 1) * HD + c] = swishf(r01.y);
            s_h2[(ty * 4 + 2) * HD + c] = swishf(r23.x);
            s_h2[(ty * 4 + 3) * HD + c] = swishf(r23.y);
        }
        if (tail) {
            float2 r01 = up2(a01[6]), r23 = up2(a23[6]);
            int c = 96 + tx;
            s_h2[(ty * 4 + 0) * HD + c] = swishf(r01.x);
            s_h2[(ty * 4 + 1) * HD + c] = swishf(r01.y);
            s_h2[(ty * 4 + 2) * HD + c] = swishf(r23.x);
            s_h2[(ty * 4 + 3) * HD + c] = swishf(r23.y);
        }
    }
    __syncthreads();

    // key_t = H2 @ WfF; score = dot(key_t, q[a])/16   (f32x2)
    {
        const int p = tid >> 2, q4 = tid & 3, ig = q4 * 4;
        u64t a01 = 0ull, a23 = 0ull;
#pragma unroll 4
        for (int m = 0; m < HD; m++) {
            u64t hh = bc2(s_h2[p * HD + m]);
            ulonglong2 w = *(const ulonglong2*)(s_wff + m * CH + ig);
            fma2(a01, hh, w.x);
            fma2(a23, hh, w.y);
        }
        const int a = a0 + p;
        float4 qv = *(const float4*)(g_q + ((h * Z + z) * NPT + a) * CH + ig);
        float2 k01 = up2(a01), k23 = up2(a23);
        float part = k01.x * qv.x + k01.y * qv.y + k23.x * qv.z + k23.y * qv.w;
        part += __shfl_xor_sync(0xffffffffu, part, 1);
        part += __shfl_xor_sync(0xffffffffu, part, 2);
        if (q4 == 0)
            g_scores[((h * Z + z) * NPT + a) * NPT + b] = part * (1.0f / CH);
    }

    // Hv = swish(basis3 @ V0) -> s_h1t transposed
    for (int e = tid; e < ATILE * HD; e += 256) {
        int m = e >> 6, p = e & 63;
        float acc = 0.f;
#pragma unroll
        for (int n = 0; n < NBV; n++) acc += s_bas3[p * NBV + n] * s_v0[n * HD + m];
        s_h1t[e] = swishf(acc);
    }
    __syncthreads();

    // val_t = Hv @ VfF  (f32x2)
    {
        const int p = tid >> 2, q4 = tid & 3, ig = q4 * 4;
        u64t a01 = 0ull, a23 = 0ull;
#pragma unroll 4
        for (int m = 0; m < HD; m++) {
            u64t hh = bc2(s_h1t[m * 64 + p]);
            ulonglong2 w = *(const ulonglong2*)(s_vff + m * CH + ig);
            fma2(a01, hh, w.x);
            fma2(a23, hh, w.y);
        }
        const int a = a0 + p;
        float2 v01 = up2(a01), v23 = up2(a23);
        float4* op = (float4*)(g_valt + ((size_t)((h * Z + z) * NPT + a) * NPT + b) * CH + ig);
        *op = make_float4(v01.x, v01.y, v23.x, v23.y);
    }
}

// ---------------- Kernel S: softmax + weighted sum (shuffle-based) ----------------
__global__ __launch_bounds__(256) void softmax_kernel() {
    const int bid = blockIdx.x;
    const int z = bid / NPT, a = bid % NPT;
    const int tid = threadIdx.x;     // = b
    const int wid = tid >> 5, lane = tid & 31;
    __shared__ float swr[8];
    __shared__ float vr[8 * CH];

    float accv[CH];
#pragma unroll
    for (int i = 0; i < CH; i++) accv[i] = 0.f;

#pragma unroll
    for (int h = 0; h < HEADS; h++) {
        float sc = g_scores[((h * Z + z) * NPT + a) * NPT + tid];
        float m = sc;
#pragma unroll
        for (int s = 16; s > 0; s >>= 1) m = fmaxf(m, __shfl_xor_sync(0xffffffffu, m, s));
        if (lane == 0) swr[wid] = m;
        __syncthreads();
        float mx = swr[0];
#pragma unroll
        for (int j = 1; j < 8; j++) mx = fmaxf(mx, swr[j]);
        __syncthreads();
        float e = __expf(sc - mx);
        float sum = e;
#pragma unroll
        for (int s = 16; s > 0; s >>= 1) sum += __shfl_xor_sync(0xffffffffu, sum, s);
        if (lane == 0) swr[wid] = sum;
        __syncthreads();
        float tot = swr[0];
#pragma unroll
        for (int j = 1; j < 8; j++) tot += swr[j];
        __syncthreads();
        float p = e / tot;

        const float4* vp = (const float4*)(g_valt +
            ((size_t)((h * Z + z) * NPT + a) * NPT + tid) * CH);
#pragma unroll
        for (int k = 0; k < 4; k++) {
            float4 v = vp[k];
            accv[k * 4 + 0] += p * v.x;
            accv[k * 4 + 1] += p * v.y;
            accv[k * 4 + 2] += p * v.z;
            accv[k * 4 + 3] += p * v.w;
        }
    }
#pragma unroll
    for (int s = 16; s > 0; s >>= 1)
#pragma unroll
        for (int i = 0; i < CH; i++) accv[i] += __shfl_xor_sync(0xffffffffu, accv[i], s);
    if (lane == 0)
#pragma unroll
        for (int i = 0; i < CH; i++) vr[wid * CH + i] = accv[i];
    __syncthreads();
    if (tid < CH) {
        float acc = 0.f;
#pragma unroll
        for (int w = 0; w < 8; w++) acc += vr[w * CH + tid];
        g_attnout[(z * NPT + a) * CH + tid] = acc;
    }
}

// ---------------- Kernel C1: CfF projection (8 points / block) ----------------
__global__ __launch_bounds__(256) void cff_kernel(const float* __restrict__ Cf) {
    const int z = blockIdx.x >> 5;
    const int b0 = (blockIdx.x & 31) * 8;
    const int tid = threadIdx.x;
    __shared__ float ao[8 * CH];
    if (tid < 8 * CH) ao[tid] = g_attnout[(z * NPT + b0) * CH + tid];
    __syncthreads();
    for (int e = tid; e < HD * CH; e += 256) {
        const int i = e & 15;
        const int m = e >> 4;
        float4 c0 = *(const float4*)(Cf + m * (CH * CH) + i * CH);
        float4 c1 = *(const float4*)(Cf + m * (CH * CH) + i * CH + 4);
        float4 c2 = *(const float4*)(Cf + m * (CH * CH) + i * CH + 8);
        float4 c3 = *(const float4*)(Cf + m * (CH * CH) + i * CH + 12);
#pragma unroll
        for (int bl = 0; bl < 8; bl++) {
            const float* f = ao + bl * CH;
            float acc = c0.x*f[0]+c0.y*f[1]+c0.z*f[2]+c0.w*f[3]
                      + c1.x*f[4]+c1.y*f[5]+c1.z*f[6]+c1.w*f[7]
                      + c2.x*f[8]+c2.y*f[9]+c2.z*f[10]+c2.w*f[11]
                      + c3.x*f[12]+c3.y*f[13]+c3.z*f[14]+c3.w*f[15];
            g_CfF[(z * NPT + b0 + bl) * (HD * CH) + e] = acc;
        }
    }
}

// ---------------- Kernel C2: final conv ----------------
#define C_SMEM_FLOATS 26104
__global__ __launch_bounds__(256, 2) void conv_kernel(const float* __restrict__ xyz,
                                                      const float* __restrict__ C0g,
                                                      const float* __restrict__ C1g,
                                                      float* __restrict__ out) {
    extern __shared__ float sm[];
    float* s_c0  = sm;                // 1000
    float* s_c1  = sm + 1000;         // 10000
    float* s_cff = sm + 11000;        // 1600
    float* s_bas = sm + 12600;        // 640
    float* s_d   = sm + 13240;        // 64
    float* s_h1t = sm + 13304;        // 6400
    float* s_h2  = sm + 19704;        // 6400

    const int tid = threadIdx.x;
    const int b = blockIdx.x;
    const int a0 = blockIdx.y * ATILE;
    const int z = blockIdx.z;

    for (int i = tid; i < NB * HD; i += 256) s_c0[i] = C0g[i];
    for (int i = tid; i < HD * HD; i += 256) s_c1[i] = C1g[i];
    {
        const int base = (z * NPT + b) * (HD * CH);
        for (int i = tid; i < HD * CH; i += 256) s_cff[i] = g_CfF[base + i];
    }
    if (tid < ATILE) {
        int a = a0 + tid;
        float bx = xyz[(z * NPT + b) * 3 + 0];
        float by = xyz[(z * NPT + b) * 3 + 1];
        float bz = xyz[(z * NPT + b) * 3 + 2];
        float dx = bx - xyz[(z * NPT + a) * 3 + 0];
        float dy = by - xyz[(z * NPT + a) * 3 + 1];
        float dz = bz - xyz[(z * NPT + a) * 3 + 2];
        s_d[tid] = sqrtf(dx * dx + dy * dy + dz * dz + 1e-12f);
    }
    __syncthreads();

    const float STEP10 = 5.0f / 9.0f;
    const float INV10 = 9.0f / 5.0f;
    for (int e = tid; e < ATILE * NB; e += 256) {
        int p = e / NB, n = e - p * NB;
        float diff = (s_d[p] - n * STEP10) * INV10;
        s_bas[e] = (fabsf(diff) < 1.0f) ? cospif(0.5f * diff) : 0.0f;
    }
    __syncthreads();

    for (int e = tid; e < ATILE * HD; e += 256) {
        int m = e >> 6, p = e & 63;
        float acc = 0.f;
#pragma unroll
        for (int n = 0; n < NB; n++) acc += s_bas[p * NB + n] * s_c0[n * HD + m];
        s_h1t[e] = swishf(acc);
    }
    __syncthreads();

    {
        const int ty = tid >> 4, tx = tid & 15;
        u64t a01[7], a23[7];
#pragma unroll
        for (int k = 0; k < 7; k++) { a01[k] = 0ull; a23[k] = 0ull; }
        const bool tail = (tx < 4);
        for (int n = 0; n < HD; n++) {
            ulonglong2 hv = *(const ulonglong2*)(s_h1t + n * 64 + ty * 4);
#pragma unroll
            for (int k = 0; k < 6; k++) {
                u64t kk = bc2(s_c1[n * HD + tx + 16 * k]);
                fma2(a01[k], hv.x, kk);
                fma2(a23[k], hv.y, kk);
            }
            if (tail) {
                u64t kk = bc2(s_c1[n * HD + 96 + tx]);
                fma2(a01[6], hv.x, kk);
                fma2(a23[6], hv.y, kk);
            }
        }
#pragma unroll
        for (int k = 0; k < 6; k++) {
            float2 r01 = up2(a01[k]), r23 = up2(a23[k]);
            int c = tx + 16 * k;
            s_h2[(ty * 4 + 0) * HD + c] = swishf(r01.x);
            s_h2[(ty * 4 + 1) * HD + c] = swishf(r01.y);
            s_h2[(ty * 4 + 2) * HD + c] = swishf(r23.x);
            s_h2[(ty * 4 + 3) * HD + c] = swishf(r23.y);
        }
        if (tail) {
            float2 r01 = up2(a01[6]), r23 = up2(a23[6]);
            int c = 96 + tx;
            s_h2[(ty * 4 + 0) * HD + c] = swishf(r01.x);
            s_h2[(ty * 4 + 1) * HD + c] = swishf(r01.y);
            s_h2[(ty * 4 + 2) * HD + c] = swishf(r23.x);
            s_h2[(ty * 4 + 3) * HD + c] = swishf(r23.y);
        }
    }
    __syncthreads();

    {
        const int p = tid >> 2, q4 = tid & 3, ig = q4 * 4;
        u64t a01 = 0ull, a23 = 0ull;
#pragma unroll 4
        for (int m = 0; m < HD; m++) {
            u64t hh = bc2(s_h2[p * HD + m]);
            ulonglong2 w = *(const ulonglong2*)(s_cff + m * CH + ig);
            fma2(a01, hh, w.x);
            fma2(a23, hh, w.y);
        }
        const int a = a0 + p;
        float2 r01 = up2(a01), r23 = up2(a23);
        float* op = out + (z * NPT + a) * CH + ig;
        atomicAdd(op + 0, r01.x);
        atomicAdd(op + 1, r01.y);
        atomicAdd(op + 2, r23.x);
        atomicAdd(op + 3, r23.y);
    }
}

// ---------------- launch ----------------
extern "C" void kernel_launch(void* const* d_in, const int* in_sizes, int n_in,
                              void* d_out, int out_size) {
    const float* features = (const float*)d_in[0];
    const float* xyz = (const float*)d_in[1];
    const float* Wq = (const float*)d_in[2];
    const float* K0 = (const float*)d_in[3];
    const float* K1 = (const float*)d_in[4];
    const float* Kf = (const float*)d_in[5];
    const float* V0 = (const float*)d_in[6];
    const float* Vf = (const float*)d_in[7];
    const float* C0 = (const float*)d_in[8];
    const float* C1 = (const float*)d_in[9];
    const float* Cf = (const float*)d_in[10];
    float* out = (float*)d_out;

    cudaFuncSetAttribute(pair_kernel, cudaFuncAttributeMaxDynamicSharedMemorySize,
                         P_SMEM_FLOATS * (int)sizeof(float));
    cudaFuncSetAttribute(conv_kernel, cudaFuncAttributeMaxDynamicSharedMemorySize,
                         C_SMEM_FLOATS * (int)sizeof(float));

    cudaMemsetAsync(d_out, 0, (size_t)out_size * sizeof(float));

    proj_kernel<<<Z * 32, 256>>>(features, Wq, Kf, Vf);
    pair_kernel<<<dim3(NPT, NPT / ATILE, Z * HEADS), 256,
                  P_SMEM_FLOATS * sizeof(float)>>>(xyz, K0, K1, V0);
    softmax_kernel<<<Z * NPT, 256>>>();
    cff_kernel<<<Z * 32, 256>>>(Cf);
    conv_kernel<<<dim3(NPT, NPT / ATILE, Z), 256,
                  C_SMEM_FLOATS * sizeof(float)>>>(xyz, C0, C1, out);
}

// round 3
// speedup vs baseline: 1.4090x; 1.0477x over previous
#include <cuda_runtime.h>
#include <math.h>

#define Z 2
#define NPT 256
#define CH 16
#define HEADS 2
#define NB 10
#define HD 100
#define NBV 3
#define ATILE 64
#define K1STR 102
#define WSTR 102

typedef unsigned long long u64t;

// ---------------- scratch ----------------
__device__ float g_q[HEADS * Z * NPT * CH];
__device__ float g_WfF[HEADS * Z * NPT * HD * CH];   // [h][z][b][i][m]  (i-major, transposed)
__device__ float g_VfF[HEADS * Z * NPT * HD * CH];   // same layout
__device__ float g_CfF[Z * NPT * HD * CH];           // [z][b][i][m]
__device__ float g_scores[HEADS * Z * NPT * NPT];
__device__ float g_valt[HEADS * Z * NPT * NPT * CH];
__device__ float g_attnout[Z * NPT * CH];
// transposed weights (reduction dim innermost)
__device__ float g_K0T[HEADS * HD * NB];     // [h][m][n]
__device__ float g_K1T[HEADS * HD * HD];     // [h][m][n]
__device__ float g_V0T[HEADS * HD * 4];      // [h][m][n], n padded to 4 with 0
__device__ float g_C0T[HD * NB];
__device__ float g_C1T[HD * HD];

__device__ __forceinline__ float swishf(float x) {
    return x / (1.0f + __expf(-x));
}
__device__ __forceinline__ void fma2(u64t& d, u64t a, u64t b) {
    asm("fma.rn.f32x2 %0, %1, %2, %0;" : "+l"(d) : "l"(a), "l"(b));
}
__device__ __forceinline__ float up2sum(u64t v) {
    float2 f;
    asm("mov.b64 {%0, %1}, %2;" : "=f"(f.x), "=f"(f.y) : "l"(v));
    return f.x + f.y;
}
__device__ __forceinline__ u64t lds64(const float* p) {
    return *(const u64t*)p;
}

// ---------------- Kernel T: one-time weight transposes ----------------
__global__ void transpose_weights(const float* __restrict__ K0,
                                  const float* __restrict__ K1,
                                  const float* __restrict__ V0,
                                  const float* __restrict__ C0,
                                  const float* __restrict__ C1) {
    int idx = blockIdx.x * blockDim.x + threadIdx.x;
    // K0T: 2*100*10 = 2000
    if (idx < 2000) {
        int h = idx / 1000, r = idx % 1000, m = r / NB, n = r % NB;
        g_K0T[idx] = K0[h * NB * HD + n * HD + m];
    }
    // K1T: 2*100*100 = 20000
    if (idx < 20000) {
        int h = idx / 10000, r = idx % 10000, m = r / HD, n = r % HD;
        g_K1T[idx] = K1[h * HD * HD + n * HD + m];
    }
    // V0T: 2*100*4 = 800
    if (idx < 800) {
        int h = idx / 400, r = idx % 400, m = r / 4, n = r % 4;
        g_V0T[idx] = (n < NBV) ? V0[h * NBV * HD + n * HD + m] : 0.0f;
    }
    // C0T: 1000
    if (idx < 1000) {
        int m = idx / NB, n = idx % NB;
        g_C0T[idx] = C0[n * HD + m];
    }
    // C1T: 10000
    if (idx < 10000) {
        int m = idx / HD, n = idx % HD;
        g_C1T[idx] = C1[n * HD + m];
    }
}

// ---------------- Kernel A: projections q, WfF, VfF (transposed out) ----------------
__global__ __launch_bounds__(256) void proj_kernel(const float* __restrict__ features,
                                                   const float* __restrict__ Wq,
                                                   const float* __restrict__ Kf,
                                                   const float* __restrict__ Vf) {
    const int z = blockIdx.x >> 5;
    const int b0 = (blockIdx.x & 31) * 8;
    const int tid = threadIdx.x;
    __shared__ float fs[8 * CH];
    if (tid < 8 * CH) fs[tid] = features[(z * NPT + b0) * CH + tid];
    __syncthreads();

    {
        const int bl = tid >> 5, r = tid & 31, h = r >> 4, o = r & 15;
        float acc = 0.f;
#pragma unroll
        for (int i = 0; i < CH; i++) acc += fs[bl * CH + i] * Wq[(h * CH + o) * CH + i];
        g_q[((h * Z + z) * NPT + b0 + bl) * CH + o] = acc;
    }

    // r = i*100 + m  (transposed output layout)
    for (int e = tid; e < HEADS * HD * CH; e += 256) {
        const int h = e / (HD * CH);
        const int r = e - h * (HD * CH);
        const int i = r / HD, m = r - i * HD;
        const float* kfp = Kf + (h * HD + m) * (CH * CH) + i * CH;
        const float* vfp = Vf + (h * HD + m) * (CH * CH) + i * CH;
        float4 k0 = *(const float4*)(kfp);
        float4 k1 = *(const float4*)(kfp + 4);
        float4 k2 = *(const float4*)(kfp + 8);
        float4 k3 = *(const float4*)(kfp + 12);
        float4 v0 = *(const float4*)(vfp);
        float4 v1 = *(const float4*)(vfp + 4);
        float4 v2 = *(const float4*)(vfp + 8);
        float4 v3 = *(const float4*)(vfp + 12);
#pragma unroll
        for (int bl = 0; bl < 8; bl++) {
            const float* f = fs + bl * CH;
            float aK = k0.x*f[0]+k0.y*f[1]+k0.z*f[2]+k0.w*f[3]
                     + k1.x*f[4]+k1.y*f[5]+k1.z*f[6]+k1.w*f[7]
                     + k2.x*f[8]+k2.y*f[9]+k2.z*f[10]+k2.w*f[11]
                     + k3.x*f[12]+k3.y*f[13]+k3.z*f[14]+k3.w*f[15];
            float aV = v0.x*f[0]+v0.y*f[1]+v0.z*f[2]+v0.w*f[3]
                     + v1.x*f[4]+v1.y*f[5]+v1.z*f[6]+v1.w*f[7]
                     + v2.x*f[8]+v2.y*f[9]+v2.z*f[10]+v2.w*f[11]
                     + v3.x*f[12]+v3.y*f[13]+v3.z*f[14]+v3.w*f[15];
            int o = ((h * Z + z) * NPT + b0 + bl) * (HD * CH) + r;
            g_WfF[o] = aK;
            g_VfF[o] = aV;
        }
    }
}

// ---------------- Kernel P: pair kernel ----------------
#define P_SMEM_FLOATS 28624
__global__ __launch_bounds__(256, 2) void pair_kernel(const float* __restrict__ xyz) {
    extern __shared__ float sm[];
    float* s_k0T  = sm;            // 1000  [m][10]
    float* s_k1T  = sm + 1000;     // 10200 [c][102]
    float* s_v0T  = sm + 11200;    // 400   [m][4]
    float* s_wffT = sm + 11600;    // 1632  [i][102]
    float* s_vffT = sm + 13232;    // 1632
    float* s_bas  = sm + 14864;    // 640   [p][10]
    float* s_bas3 = sm + 15504;    // 256   [p][4]
    float* s_d    = sm + 15760;    // 64
    float* s_h1   = sm + 15824;    // 6400  [p][100]
    float* s_h2   = sm + 22224;    // 6400  [p][100]

    const int tid = threadIdx.x;
    const int b = blockIdx.x;
    const int a0 = blockIdx.y * ATILE;
    const int z = blockIdx.z >> 1;
    const int h = blockIdx.z & 1;

    for (int i = tid; i < HD * NB; i += 256) s_k0T[i] = g_K0T[h * HD * NB + i];
    for (int e = tid; e < HD * HD; e += 256) {
        int m = e / HD, n = e - m * HD;
        s_k1T[m * K1STR + n] = g_K1T[h * HD * HD + e];
    }
    for (int i = tid; i < HD * 4; i += 256) s_v0T[i] = g_V0T[h * HD * 4 + i];
    {
        const int base = ((h * Z + z) * NPT + b) * (HD * CH);
        for (int e = tid; e < HD * CH; e += 256) {
            int i = e / HD, m = e - i * HD;
            s_wffT[i * WSTR + m] = g_WfF[base + e];
            s_vffT[i * WSTR + m] = g_VfF[base + e];
        }
    }
    if (tid < ATILE) {
        int a = a0 + tid;
        float bx = xyz[(z * NPT + b) * 3 + 0];
        float by = xyz[(z * NPT + b) * 3 + 1];
        float bz = xyz[(z * NPT + b) * 3 + 2];
        float dx = bx - xyz[(z * NPT + a) * 3 + 0];
        float dy = by - xyz[(z * NPT + a) * 3 + 1];
        float dz = bz - xyz[(z * NPT + a) * 3 + 2];
        s_d[tid] = sqrtf(dx * dx + dy * dy + dz * dz + 1e-12f);
    }
    __syncthreads();

    const float STEP10 = 5.0f / 9.0f;
    const float INV10 = 9.0f / 5.0f;
    for (int e = tid; e < ATILE * NB; e += 256) {
        int p = e / NB, n = e - p * NB;
        float diff = (s_d[p] - n * STEP10) * INV10;
        s_bas[e] = (fabsf(diff) < 1.0f) ? cospif(0.5f * diff) : 0.0f;
    }
    for (int e = tid; e < ATILE * 4; e += 256) {
        int p = e >> 2, n = e & 3;
        float diff = (s_d[p] - n * 2.5f) * 0.4f;
        s_bas3[e] = (n < NBV && fabsf(diff) < 1.0f) ? cospif(0.5f * diff) : 0.0f;
    }
    __syncthreads();

    // H1 = swish(basis @ K0): n-pair f32x2, basis hoisted per thread
    {
        const int p = tid >> 2, q4 = tid & 3;
        const float* bp = s_bas + p * NB;
        u64t bb0 = lds64(bp), bb1 = lds64(bp + 2), bb2 = lds64(bp + 4),
             bb3 = lds64(bp + 6), bb4 = lds64(bp + 8);
#pragma unroll 5
        for (int mm = 0; mm < 25; mm++) {
            int m = q4 * 25 + mm;
            const float* kp = s_k0T + m * NB;
            u64t acc = 0ull;
            fma2(acc, bb0, lds64(kp));
            fma2(acc, bb1, lds64(kp + 2));
            fma2(acc, bb2, lds64(kp + 4));
            fma2(acc, bb3, lds64(kp + 6));
            fma2(acc, bb4, lds64(kp + 8));
            s_h1[p * HD + m] = swishf(up2sum(acc));
        }
    }
    __syncthreads();

    // H2 = swish(H1 @ K1): both operands n-pairs, no broadcasts
    {
        const int ty = tid >> 4, tx = tid & 15;
        const float* hbase = s_h1 + ty * 4 * HD;
        const bool tail = tx < 4;
        u64t acc[4][7];
#pragma unroll
        for (int r = 0; r < 4; r++)
#pragma unroll
            for (int j = 0; j < 7; j++) acc[r][j] = 0ull;
#pragma unroll 2
        for (int t = 0; t < 50; t++) {
            u64t h0 = lds64(hbase + 2 * t);
            u64t h1v = lds64(hbase + HD + 2 * t);
            u64t h2v = lds64(hbase + 2 * HD + 2 * t);
            u64t h3v = lds64(hbase + 3 * HD + 2 * t);
#pragma unroll
            for (int j = 0; j < 6; j++) {
                u64t kv = lds64(s_k1T + (tx + 16 * j) * K1STR + 2 * t);
                fma2(acc[0][j], h0, kv);
                fma2(acc[1][j], h1v, kv);
                fma2(acc[2][j], h2v, kv);
                fma2(acc[3][j], h3v, kv);
            }
            if (tail) {
                u64t kv = lds64(s_k1T + (tx + 96) * K1STR + 2 * t);
                fma2(acc[0][6], h0, kv);
                fma2(acc[1][6], h1v, kv);
                fma2(acc[2][6], h2v, kv);
                fma2(acc[3][6], h3v, kv);
            }
        }
#pragma unroll
        for (int r = 0; r < 4; r++) {
#pragma unroll
            for (int j = 0; j < 6; j++)
                s_h2[(ty * 4 + r) * HD + tx + 16 * j] = swishf(up2sum(acc[r][j]));
            if (tail)
                s_h2[(ty * 4 + r) * HD + tx + 96] = swishf(up2sum(acc[r][6]));
        }
    }
    __syncthreads();

    // key_t = H2 @ WfF; score = dot(key_t, q)/16.  2 pairs x 4 i x 2-way m-split.
    {
        const int mc = tid >> 7, r7 = tid & 127, pg = r7 >> 2, q4 = r7 & 3, ig = q4 * 4;
        const int p0 = 2 * pg, p1 = p0 + 1;
        const float* h2a = s_h2 + p0 * HD + mc * 50;
        const float* h2b = s_h2 + p1 * HD + mc * 50;
        const float* wb = s_wffT + ig * WSTR + mc * 50;
        u64t accA[4] = {0ull, 0ull, 0ull, 0ull};
        u64t accB[4] = {0ull, 0ull, 0ull, 0ull};
#pragma unroll 5
        for (int u = 0; u < 25; u++) {
            u64t hA = lds64(h2a + 2 * u);
            u64t hB = lds64(h2b + 2 * u);
#pragma unroll
            for (int ii = 0; ii < 4; ii++) {
                u64t w = lds64(wb + ii * WSTR + 2 * u);
                fma2(accA[ii], hA, w);
                fma2(accB[ii], hB, w);
            }
        }
        float ka[4], kb[4];
#pragma unroll
        for (int ii = 0; ii < 4; ii++) { ka[ii] = up2sum(accA[ii]); kb[ii] = up2sum(accB[ii]); }
        float* scr = s_h1;  // H1 dead; reuse as scratch
        if (mc == 1) {
#pragma unroll
            for (int ii = 0; ii < 4; ii++) {
                scr[ii * 128 + r7] = ka[ii];
                scr[(4 + ii) * 128 + r7] = kb[ii];
            }
        }
        __syncthreads();
        if (mc == 0) {
#pragma unroll
            for (int ii = 0; ii < 4; ii++) {
                ka[ii] += scr[ii * 128 + r7];
                kb[ii] += scr[(4 + ii) * 128 + r7];
            }
            const int aA = a0 + p0, aB = a0 + p1;
            float4 qA = *(const float4*)(g_q + ((h * Z + z) * NPT + aA) * CH + ig);
            float4 qB = *(const float4*)(g_q + ((h * Z + z) * NPT + aB) * CH + ig);
            float sA = ka[0]*qA.x + ka[1]*qA.y + ka[2]*qA.z + ka[3]*qA.w;
            float sB = kb[0]*qB.x + kb[1]*qB.y + kb[2]*qB.z + kb[3]*qB.w;
            sA += __shfl_xor_sync(0xffffffffu, sA, 1);
            sA += __shfl_xor_sync(0xffffffffu, sA, 2);
            sB += __shfl_xor_sync(0xffffffffu, sB, 1);
            sB += __shfl_xor_sync(0xffffffffu, sB, 2);
            if (q4 == 0) {
                g_scores[((h * Z + z) * NPT + aA) * NPT + b] = sA * (1.0f / CH);
                g_scores[((h * Z + z) * NPT + aB) * NPT + b] = sB * (1.0f / CH);
            }
        }
        __syncthreads();
    }

    // Hv = swish(basis3 @ V0) into s_h1
    {
        const int p = tid >> 2, q4 = tid & 3;
        u64t b01 = lds64(s_bas3 + p * 4);
        u64t b23 = lds64(s_bas3 + p * 4 + 2);
#pragma unroll 5
        for (int mm = 0; mm < 25; mm++) {
            int m = q4 * 25 + mm;
            const float* vp = s_v0T + m * 4;
            u64t acc = 0ull;
            fma2(acc, b01, lds64(vp));
            fma2(acc, b23, lds64(vp + 2));
            s_h1[p * HD + m] = swishf(up2sum(acc));
        }
    }
    __syncthreads();

    // val_t = Hv @ VfF
    {
        const int mc = tid >> 7, r7 = tid & 127, pg = r7 >> 2, q4 = r7 & 3, ig = q4 * 4;
        const int p0 = 2 * pg, p1 = p0 + 1;
        const float* hva = s_h1 + p0 * HD + mc * 50;
        const float* hvb = s_h1 + p1 * HD + mc * 50;
        const float* wb = s_vffT + ig * WSTR + mc * 50;
        u64t accA[4] = {0ull, 0ull, 0ull, 0ull};
        u64t accB[4] = {0ull, 0ull, 0ull, 0ull};
#pragma unroll 5
        for (int u = 0; u < 25; u++) {
            u64t hA = lds64(hva + 2 * u);
            u64t hB = lds64(hvb + 2 * u);
#pragma unroll
            for (int ii = 0; ii < 4; ii++) {
                u64t w = lds64(wb + ii * WSTR + 2 * u);
                fma2(accA[ii], hA, w);
                fma2(accB[ii], hB, w);
            }
        }
        float va[4], vb[4];
#pragma unroll
        for (int ii = 0; ii < 4; ii++) { va[ii] = up2sum(accA[ii]); vb[ii] = up2sum(accB[ii]); }
        float* scr = s_h2;  // H2 dead; reuse
        if (mc == 1) {
#pragma unroll
            for (int ii = 0; ii < 4; ii++) {
                scr[ii * 128 + r7] = va[ii];
                scr[(4 + ii) * 128 + r7] = vb[ii];
            }
        }
        __syncthreads();
        if (mc == 0) {
#pragma unroll
            for (int ii = 0; ii < 4; ii++) {
                va[ii] += scr[ii * 128 + r7];
                vb[ii] += scr[(4 + ii) * 128 + r7];
            }
            const int aA = a0 + p0, aB = a0 + p1;
            size_t baseA = ((size_t)((h * Z + z) * NPT + aA) * NPT + b) * CH + ig;
            size_t baseB = ((size_t)((h * Z + z) * NPT + aB) * NPT + b) * CH + ig;
            *(float4*)(g_valt + baseA) = make_float4(va[0], va[1], va[2], va[3]);
            *(float4*)(g_valt + baseB) = make_float4(vb[0], vb[1], vb[2], vb[3]);
        }
    }
}

// ---------------- Kernel S: softmax + weighted sum ----------------
__global__ __launch_bounds__(256) void softmax_kernel() {
    const int bid = blockIdx.x;
    const int z = bid / NPT, a = bid % NPT;
    const int tid = threadIdx.x;
    const int wid = tid >> 5, lane = tid & 31;
    __shared__ float swr[8];
    __shared__ float vr[8 * CH];

    float accv[CH];
#pragma unroll
    for (int i = 0; i < CH; i++) accv[i] = 0.f;

#pragma unroll
    for (int h = 0; h < HEADS; h++) {
        float sc = g_scores[((h * Z + z) * NPT + a) * NPT + tid];
        float m = sc;
#pragma unroll
        for (int s = 16; s > 0; s >>= 1) m = fmaxf(m, __shfl_xor_sync(0xffffffffu, m, s));
        if (lane == 0) swr[wid] = m;
        __syncthreads();
        float mx = swr[0];
#pragma unroll
        for (int j = 1; j < 8; j++) mx = fmaxf(mx, swr[j]);
        __syncthreads();
        float e = __expf(sc - mx);
        float sum = e;
#pragma unroll
        for (int s = 16; s > 0; s >>= 1) sum += __shfl_xor_sync(0xffffffffu, sum, s);
        if (lane == 0) swr[wid] = sum;
        __syncthreads();
        float tot = swr[0];
#pragma unroll
        for (int j = 1; j < 8; j++) tot += swr[j];
        __syncthreads();
        float p = e / tot;

        const float4* vp = (const float4*)(g_valt +
            ((size_t)((h * Z + z) * NPT + a) * NPT + tid) * CH);
#pragma unroll
        for (int k = 0; k < 4; k++) {
            float4 v = vp[k];
            accv[k * 4 + 0] += p * v.x;
            accv[k * 4 + 1] += p * v.y;
            accv[k * 4 + 2] += p * v.z;
            accv[k * 4 + 3] += p * v.w;
        }
    }
#pragma unroll
    for (int s = 16; s > 0; s >>= 1)
#pragma unroll
        for (int i = 0; i < CH; i++) accv[i] += __shfl_xor_sync(0xffffffffu, accv[i], s);
    if (lane == 0)
#pragma unroll
        for (int i = 0; i < CH; i++) vr[wid * CH + i] = accv[i];
    __syncthreads();
    if (tid < CH) {
        float acc = 0.f;
#pragma unroll
        for (int w = 0; w < 8; w++) acc += vr[w * CH + tid];
        g_attnout[(z * NPT + a) * CH + tid] = acc;
    }
}

// ---------------- Kernel C1: CfF projection (transposed out) ----------------
__global__ __launch_bounds__(256) void cff_kernel(const float* __restrict__ Cf) {
    const int z = blockIdx.x >> 5;
    const int b0 = (blockIdx.x & 31) * 8;
    const int tid = threadIdx.x;
    __shared__ float ao[8 * CH];
    if (tid < 8 * CH) ao[tid] = g_attnout[(z * NPT + b0) * CH + tid];
    __syncthreads();
    for (int e = tid; e < HD * CH; e += 256) {
        const int i = e / HD, m = e - i * HD;
        const float* cp = Cf + m * (CH * CH) + i * CH;
        float4 c0 = *(const float4*)(cp);
        float4 c1 = *(const float4*)(cp + 4);
        float4 c2 = *(const float4*)(cp + 8);
        float4 c3 = *(const float4*)(cp + 12);
#pragma unroll
        for (int bl = 0; bl < 8; bl++) {
            const float* f = ao + bl * CH;
            float acc = c0.x*f[0]+c0.y*f[1]+c0.z*f[2]+c0.w*f[3]
                      + c1.x*f[4]+c1.y*f[5]+c1.z*f[6]+c1.w*f[7]
                      + c2.x*f[8]+c2.y*f[9]+c2.z*f[10]+c2.w*f[11]
                      + c3.x*f[12]+c3.y*f[13]+c3.z*f[14]+c3.w*f[15];
            g_CfF[(z * NPT + b0 + bl) * (HD * CH) + e] = acc;
        }
    }
}

// ---------------- Kernel C2: final conv ----------------
#define C_SMEM_FLOATS 26336
__global__ __launch_bounds__(256, 2) void conv_kernel(const float* __restrict__ xyz,
                                                      float* __restrict__ out) {
    extern __shared__ float sm[];
    float* s_c0T  = sm;            // 1000
    float* s_c1T  = sm + 1000;     // 10200
    float* s_cffT = sm + 11200;    // 1632
    float* s_bas  = sm + 12832;    // 640
    float* s_d    = sm + 13472;    // 64
    float* s_h1   = sm + 13536;    // 6400
    float* s_h2   = sm + 19936;    // 6400

    const int tid = threadIdx.x;
    const int b = blockIdx.x;
    const int a0 = blockIdx.y * ATILE;
    const int z = blockIdx.z;

    for (int i = tid; i < HD * NB; i += 256) s_c0T[i] = g_C0T[i];
    for (int e = tid; e < HD * HD; e += 256) {
        int m = e / HD, n = e - m * HD;
        s_c1T[m * K1STR + n] = g_C1T[e];
    }
    {
        const int base = (z * NPT + b) * (HD * CH);
        for (int e = tid; e < HD * CH; e += 256) {
            int i = e / HD, m = e - i * HD;
            s_cffT[i * WSTR + m] = g_CfF[base + e];
        }
    }
    if (tid < ATILE) {
        int a = a0 + tid;
        float bx = xyz[(z * NPT + b) * 3 + 0];
        float by = xyz[(z * NPT + b) * 3 + 1];
        float bz = xyz[(z * NPT + b) * 3 + 2];
        float dx = bx - xyz[(z * NPT + a) * 3 + 0];
        float dy = by - xyz[(z * NPT + a) * 3 + 1];
        float dz = bz - xyz[(z * NPT + a) * 3 + 2];
        s_d[tid] = sqrtf(dx * dx + dy * dy + dz * dz + 1e-12f);
    }
    __syncthreads();

    const float STEP10 = 5.0f / 9.0f;
    const float INV10 = 9.0f / 5.0f;
    for (int e = tid; e < ATILE * NB; e += 256) {
        int p = e / NB, n = e - p * NB;
        float diff = (s_d[p] - n * STEP10) * INV10;
        s_bas[e] = (fabsf(diff) < 1.0f) ? cospif(0.5f * diff) : 0.0f;
    }
    __syncthreads();

    {
        const int p = tid >> 2, q4 = tid & 3;
        const float* bp = s_bas + p * NB;
        u64t bb0 = lds64(bp), bb1 = lds64(bp + 2), bb2 = lds64(bp + 4),
             bb3 = lds64(bp + 6), bb4 = lds64(bp + 8);
#pragma unroll 5
        for (int mm = 0; mm < 25; mm++) {
            int m = q4 * 25 + mm;
            const float* kp = s_c0T + m * NB;
            u64t acc = 0ull;
            fma2(acc, bb0, lds64(kp));
            fma2(acc, bb1, lds64(kp + 2));
            fma2(acc, bb2, lds64(kp + 4));
            fma2(acc, bb3, lds64(kp + 6));
            fma2(acc, bb4, lds64(kp + 8));
            s_h1[p * HD + m] = swishf(up2sum(acc));
        }
    }
    __syncthreads();

    {
        const int ty = tid >> 4, tx = tid & 15;
        const float* hbase = s_h1 + ty * 4 * HD;
        const bool tail = tx < 4;
        u64t acc[4][7];
#pragma unroll
        for (int r = 0; r < 4; r++)
#pragma unroll
            for (int j = 0; j < 7; j++) acc[r][j] = 0ull;
#pragma unroll 2
        for (int t = 0; t < 50; t++) {
            u64t h0 = lds64(hbase + 2 * t);
            u64t h1v = lds64(hbase + HD + 2 * t);
            u64t h2v = lds64(hbase + 2 * HD + 2 * t);
            u64t h3v = lds64(hbase + 3 * HD + 2 * t);
#pragma unroll
            for (int j = 0; j < 6; j++) {
                u64t kv = lds64(s_c1T + (tx + 16 * j) * K1STR + 2 * t);
                fma2(acc[0][j], h0, kv);
                fma2(acc[1][j], h1v, kv);
                fma2(acc[2][j], h2v, kv);
                fma2(acc[3][j], h3v, kv);
            }
            if (tail) {
                u64t kv = lds64(s_c1T + (tx + 96) * K1STR + 2 * t);
                fma2(acc[0][6], h0, kv);
                fma2(acc[1][6], h1v, kv);
                fma2(acc[2][6], h2v, kv);
                fma2(acc[3][6], h3v, kv);
            }
        }
#pragma unroll
        for (int r = 0; r < 4; r++) {
#pragma unroll
            for (int j = 0; j < 6; j++)
                s_h2[(ty * 4 + r) * HD + tx + 16 * j] = swishf(up2sum(acc[r][j]));
            if (tail)
                s_h2[(ty * 4 + r) * HD + tx + 96] = swishf(up2sum(acc[r][6]));
        }
    }
    __syncthreads();

    {
        const int mc = tid >> 7, r7 = tid & 127, pg = r7 >> 2, q4 = r7 & 3, ig = q4 * 4;
        const int p0 = 2 * pg, p1 = p0 + 1;
        const float* h2a = s_h2 + p0 * HD + mc * 50;
        const float* h2b = s_h2 + p1 * HD + mc * 50;
        const float* wb = s_cffT + ig * WSTR + mc * 50;
        u64t accA[4] = {0ull, 0ull, 0ull, 0ull};
        u64t accB[4] = {0ull, 0ull, 0ull, 0ull};
#pragma unroll 5
        for (int u = 0; u < 25; u++) {
            u64t hA = lds64(h2a + 2 * u);
            u64t hB = lds64(h2b + 2 * u);
#pragma unroll
            for (int ii = 0; ii < 4; ii++) {
                u64t w = lds64(wb + ii * WSTR + 2 * u);
                fma2(accA[ii], hA, w);
                fma2(accB[ii], hB, w);
            }
        }
        float va[4], vb[4];
#pragma unroll
        for (int ii = 0; ii < 4; ii++) { va[ii] = up2sum(accA[ii]); vb[ii] = up2sum(accB[ii]); }
        float* scr = s_h1;
        if (mc == 1) {
#pragma unroll
            for (int ii = 0; ii < 4; ii++) {
                scr[ii * 128 + r7] = va[ii];
                scr[(4 + ii) * 128 + r7] = vb[ii];
            }
        }
        __syncthreads();
        if (mc == 0) {
            const int aA = a0 + p0, aB = a0 + p1;
            float* opA = out + (z * NPT + aA) * CH + ig;
            float* opB = out + (z * NPT + aB) * CH + ig;
#pragma unroll
            for (int ii = 0; ii < 4; ii++) {
                atomicAdd(opA + ii, va[ii] + scr[ii * 128 + r7]);
                atomicAdd(opB + ii, vb[ii] + scr[(4 + ii) * 128 + r7]);
            }
        }
    }
}

// ---------------- launch ----------------
extern "C" void kernel_launch(void* const* d_in, const int* in_sizes, int n_in,
                              void* d_out, int out_size) {
    const float* features = (const float*)d_in[0];
    const float* xyz = (const float*)d_in[1];
    const float* Wq = (const float*)d_in[2];
    const float* K0 = (const float*)d_in[3];
    const float* K1 = (const float*)d_in[4];
    const float* Kf = (const float*)d_in[5];
    const float* V0 = (const float*)d_in[6];
    const float* Vf = (const float*)d_in[7];
    const float* C0 = (const float*)d_in[8];
    const float* C1 = (const float*)d_in[9];
    const float* Cf = (const float*)d_in[10];
    float* out = (float*)d_out;

    cudaFuncSetAttribute(pair_kernel, cudaFuncAttributeMaxDynamicSharedMemorySize,
                         P_SMEM_FLOATS * (int)sizeof(float));
    cudaFuncSetAttribute(conv_kernel, cudaFuncAttributeMaxDynamicSharedMemorySize,
                         C_SMEM_FLOATS * (int)sizeof(float));

    cudaMemsetAsync(d_out, 0, (size_t)out_size * sizeof(float));

    transpose_weights<<<79, 256>>>(K0, K1, V0, C0, C1);
    proj_kernel<<<Z * 32, 256>>>(features, Wq, Kf, Vf);
    pair_kernel<<<dim3(NPT, NPT / ATILE, Z * HEADS), 256,
                  P_SMEM_FLOATS * sizeof(float)>>>(xyz);
    softmax_kernel<<<Z * NPT, 256>>>();
    cff_kernel<<<Z * 32, 256>>>(Cf);
    conv_kernel<<<dim3(NPT, NPT / ATILE, Z), 256,
                  C_SMEM_FLOATS * sizeof(float)>>>(xyz, out);
}

// round 4
// speedup vs baseline: 3.0283x; 2.1492x over previous
#include <cuda_runtime.h>
#include <math.h>

#define Z 2
#define NPT 256
#define CH 16
#define HEADS 2
#define NB 10
#define HD 100
#define NBV 3
#define ATILE 64
#define K1STR 102
#define WSTR 102
#define NTAB 8192
#define DMAX 8.7f
#define STEP10 (5.0f / 9.0f)
#define INV10 (9.0f / 5.0f)

typedef unsigned long long u64t;

// ---------------- scratch ----------------
__device__ float g_q[HEADS * Z * NPT * CH];
__device__ float g_WfF[HEADS * Z * NPT * HD * CH];   // [h][z][b][i][m]
__device__ float g_VfF[HEADS * Z * NPT * HD * CH];
__device__ float g_CfF[Z * NPT * HD * CH];
__device__ float g_scores[HEADS * Z * NPT * NPT];
__device__ float g_valt[HEADS * Z * NPT * NPT * CH];
__device__ float g_attnout[Z * NPT * CH];
// transposed weights for table build
__device__ float g_K0T[HEADS * HD * NB];
__device__ float g_K1T[HEADS * HD * HD];
__device__ float g_C0T[HD * NB];
__device__ float g_C1T[HD * HD];
// radial lookup tables: H2(d) / Hv(d) sampled on NTAB points over [0, DMAX]
__device__ float g_Ktab[HEADS * NTAB * HD];
__device__ float g_Ctab[NTAB * HD];
__device__ float g_Vtab[HEADS * NTAB * HD];

__device__ __forceinline__ float swishf(float x) {
    return x / (1.0f + __expf(-x));
}
__device__ __forceinline__ void fma2(u64t& d, u64t a, u64t b) {
    asm("fma.rn.f32x2 %0, %1, %2, %0;" : "+l"(d) : "l"(a), "l"(b));
}
__device__ __forceinline__ float up2sum(u64t v) {
    float2 f;
    asm("mov.b64 {%0, %1}, %2;" : "=f"(f.x), "=f"(f.y) : "l"(v));
    return f.x + f.y;
}
__device__ __forceinline__ u64t lds64(const float* p) {
    return *(const u64t*)p;
}

// ---------------- Kernel T: weight transposes ----------------
__global__ void transpose_weights(const float* __restrict__ K0,
                                  const float* __restrict__ K1,
                                  const float* __restrict__ C0,
                                  const float* __restrict__ C1) {
    int idx = blockIdx.x * blockDim.x + threadIdx.x;
    if (idx < 2000) {
        int h = idx / 1000, r = idx % 1000, m = r / NB, n = r % NB;
        g_K0T[idx] = K0[h * NB * HD + n * HD + m];
    }
    if (idx < 20000) {
        int h = idx / 10000, r = idx % 10000, m = r / HD, n = r % HD;
        g_K1T[idx] = K1[h * HD * HD + n * HD + m];
    }
    if (idx < 1000) {
        int m = idx / NB, n = idx % NB;
        g_C0T[idx] = C0[n * HD + m];
    }
    if (idx < 10000) {
        int m = idx / HD, n = idx % HD;
        g_C1T[idx] = C1[n * HD + m];
    }
}

// ---------------- Kernel TB2: build radial2 tables (K head0/1, C) ----------------
#define T2_SMEM_FLOATS 18240
__global__ __launch_bounds__(256) void table2_kernel() {
    extern __shared__ float sm[];
    float* s_k0T = sm;            // 1000
    float* s_k1T = sm + 1000;     // 10200
    float* s_bas = sm + 11200;    // 640
    float* s_h1  = sm + 11840;    // 6400

    const int tid = threadIdx.x;
    const int net = blockIdx.y;   // 0,1 = K heads; 2 = conv
    const int p0 = blockIdx.x * 64;

    const float* K0src = (net < 2) ? (g_K0T + net * HD * NB) : g_C0T;
    const float* K1src = (net < 2) ? (g_K1T + net * HD * HD) : g_C1T;
    float* tab = (net < 2) ? (g_Ktab + (size_t)net * NTAB * HD) : g_Ctab;

    for (int i = tid; i < HD * NB; i += 256) s_k0T[i] = K0src[i];
    for (int e = tid; e < HD * HD; e += 256) {
        int m = e / HD, n = e - m * HD;
        s_k1T[m * K1STR + n] = K1src[e];
    }
    const float DELTA = DMAX / (float)(NTAB - 1);
    for (int e = tid; e < 64 * NB; e += 256) {
        int p = e / NB, n = e - p * NB;
        float d = (float)(p0 + p) * DELTA;
        float diff = (d - n * STEP10) * INV10;
        s_bas[e] = (fabsf(diff) < 1.0f) ? cospif(0.5f * diff) : 0.0f;
    }
    __syncthreads();

    // H1 = swish(basis @ K0)
    {
        const int p = tid >> 2, q4 = tid & 3;
        const float* bp = s_bas + p * NB;
        u64t bb0 = lds64(bp), bb1 = lds64(bp + 2), bb2 = lds64(bp + 4),
             bb3 = lds64(bp + 6), bb4 = lds64(bp + 8);
#pragma unroll 5
        for (int mm = 0; mm < 25; mm++) {
            int m = q4 * 25 + mm;
            const float* kp = s_k0T + m * NB;
            u64t acc = 0ull;
            fma2(acc, bb0, lds64(kp));
            fma2(acc, bb1, lds64(kp + 2));
            fma2(acc, bb2, lds64(kp + 4));
            fma2(acc, bb3, lds64(kp + 6));
            fma2(acc, bb4, lds64(kp + 8));
            s_h1[p * HD + m] = swishf(up2sum(acc));
        }
    }
    __syncthreads();

    // H2 = swish(H1 @ K1) -> global table
    {
        const int ty = tid >> 4, tx = tid & 15;
        const float* hbase = s_h1 + ty * 4 * HD;
        const bool tail = tx < 4;
        u64t acc[4][7];
#pragma unroll
        for (int r = 0; r < 4; r++)
#pragma unroll
            for (int j = 0; j < 7; j++) acc[r][j] = 0ull;
#pragma unroll 2
        for (int t = 0; t < 50; t++) {
            u64t h0 = lds64(hbase + 2 * t);
            u64t h1v = lds64(hbase + HD + 2 * t);
            u64t h2v = lds64(hbase + 2 * HD + 2 * t);
            u64t h3v = lds64(hbase + 3 * HD + 2 * t);
#pragma unroll
            for (int j = 0; j < 6; j++) {
                u64t kv = lds64(s_k1T + (tx + 16 * j) * K1STR + 2 * t);
                fma2(acc[0][j], h0, kv);
                fma2(acc[1][j], h1v, kv);
                fma2(acc[2][j], h2v, kv);
                fma2(acc[3][j], h3v, kv);
            }
            if (tail) {
                u64t kv = lds64(s_k1T + (tx + 96) * K1STR + 2 * t);
                fma2(acc[0][6], h0, kv);
                fma2(acc[1][6], h1v, kv);
                fma2(acc[2][6], h2v, kv);
                fma2(acc[3][6], h3v, kv);
            }
        }
#pragma unroll
        for (int r = 0; r < 4; r++) {
            float* row = tab + (size_t)(p0 + ty * 4 + r) * HD;
#pragma unroll
            for (int j = 0; j < 6; j++)
                row[tx + 16 * j] = swishf(up2sum(acc[r][j]));
            if (tail)
                row[tx + 96] = swishf(up2sum(acc[r][6]));
        }
    }
}

// ---------------- Kernel TB1: build radial1 value tables ----------------
__global__ __launch_bounds__(256) void table1_kernel(const float* __restrict__ V0) {
    const int h = blockIdx.y;
    const int p0 = blockIdx.x * 64;
    const int tid = threadIdx.x;
    const int p = tid >> 2, q = tid & 3;
    const float DELTA = DMAX / (float)(NTAB - 1);
    float d = (float)(p0 + p) * DELTA;
    float bas[NBV];
#pragma unroll
    for (int n = 0; n < NBV; n++) {
        float diff = (d - n * 2.5f) * 0.4f;
        bas[n] = (fabsf(diff) < 1.0f) ? cospif(0.5f * diff) : 0.0f;
    }
    const float* v = V0 + h * NBV * HD;
    float* row = g_Vtab + (size_t)h * NTAB * HD + (size_t)(p0 + p) * HD;
#pragma unroll 5
    for (int u = 0; u < 25; u++) {
        int m = q * 25 + u;
        float acc = bas[0] * v[m] + bas[1] * v[HD + m] + bas[2] * v[2 * HD + m];
        row[m] = swishf(acc);
    }
}

// ---------------- Kernel A: projections q, WfF, VfF ----------------
__global__ __launch_bounds__(256) void proj_kernel(const float* __restrict__ features,
                                                   const float* __restrict__ Wq,
                                                   const float* __restrict__ Kf,
                                                   const float* __restrict__ Vf) {
    const int z = blockIdx.x >> 5;
    const int b0 = (blockIdx.x & 31) * 8;
    const int tid = threadIdx.x;
    __shared__ float fs[8 * CH];
    if (tid < 8 * CH) fs[tid] = features[(z * NPT + b0) * CH + tid];
    __syncthreads();

    {
        const int bl = tid >> 5, r = tid & 31, h = r >> 4, o = r & 15;
        float acc = 0.f;
#pragma unroll
        for (int i = 0; i < CH; i++) acc += fs[bl * CH + i] * Wq[(h * CH + o) * CH + i];
        g_q[((h * Z + z) * NPT + b0 + bl) * CH + o] = acc;
    }

    for (int e = tid; e < HEADS * HD * CH; e += 256) {
        const int h = e / (HD * CH);
        const int r = e - h * (HD * CH);
        const int i = r / HD, m = r - i * HD;
        const float* kfp = Kf + (h * HD + m) * (CH * CH) + i * CH;
        const float* vfp = Vf + (h * HD + m) * (CH * CH) + i * CH;
        float4 k0 = *(const float4*)(kfp);
        float4 k1 = *(const float4*)(kfp + 4);
        float4 k2 = *(const float4*)(kfp + 8);
        float4 k3 = *(const float4*)(kfp + 12);
        float4 v0 = *(const float4*)(vfp);
        float4 v1 = *(const float4*)(vfp + 4);
        float4 v2 = *(const float4*)(vfp + 8);
        float4 v3 = *(const float4*)(vfp + 12);
#pragma unroll
        for (int bl = 0; bl < 8; bl++) {
            const float* f = fs + bl * CH;
            float aK = k0.x*f[0]+k0.y*f[1]+k0.z*f[2]+k0.w*f[3]
                     + k1.x*f[4]+k1.y*f[5]+k1.z*f[6]+k1.w*f[7]
                     + k2.x*f[8]+k2.y*f[9]+k2.z*f[10]+k2.w*f[11]
                     + k3.x*f[12]+k3.y*f[13]+k3.z*f[14]+k3.w*f[15];
            float aV = v0.x*f[0]+v0.y*f[1]+v0.z*f[2]+v0.w*f[3]
                     + v1.x*f[4]+v1.y*f[5]+v1.z*f[6]+v1.w*f[7]
                     + v2.x*f[8]+v2.y*f[9]+v2.z*f[10]+v2.w*f[11]
                     + v3.x*f[12]+v3.y*f[13]+v3.z*f[14]+v3.w*f[15];
            int o = ((h * Z + z) * NPT + b0 + bl) * (HD * CH) + r;
            g_WfF[o] = aK;
            g_VfF[o] = aV;
        }
    }
}

// ---------------- Kernel P: pair kernel (table-based) ----------------
#define P_SMEM_FLOATS 17152
__global__ __launch_bounds__(256) void pair_kernel(const float* __restrict__ xyz) {
    extern __shared__ float sm[];
    float* s_wffT = sm;            // 1632  [i][102]
    float* s_vffT = sm + 1632;     // 1632
    float* s_h2   = sm + 3264;     // 6400  [p][100]
    float* s_hv   = sm + 9664;     // 6400
    float* s_d    = sm + 16064;    // 64
    float* s_scr  = sm + 16128;    // 1024

    const int tid = threadIdx.x;
    const int b = blockIdx.x;
    const int a0 = blockIdx.y * ATILE;
    const int z = blockIdx.z >> 1;
    const int h = blockIdx.z & 1;

    {
        const int base = ((h * Z + z) * NPT + b) * (HD * CH);
        for (int e = tid; e < HD * CH; e += 256) {
            int i = e / HD, m = e - i * HD;
            s_wffT[i * WSTR + m] = g_WfF[base + e];
            s_vffT[i * WSTR + m] = g_VfF[base + e];
        }
    }
    if (tid < ATILE) {
        int a = a0 + tid;
        float bx = xyz[(z * NPT + b) * 3 + 0];
        float by = xyz[(z * NPT + b) * 3 + 1];
        float bz = xyz[(z * NPT + b) * 3 + 2];
        float dx = bx - xyz[(z * NPT + a) * 3 + 0];
        float dy = by - xyz[(z * NPT + a) * 3 + 1];
        float dz = bz - xyz[(z * NPT + a) * 3 + 2];
        s_d[tid] = sqrtf(dx * dx + dy * dy + dz * dz + 1e-12f);
    }
    __syncthreads();

    // gather + lerp from tables (H2 and Hv share index/frac)
    {
        const int p = tid >> 2, q = tid & 3;
        const float TSCALE = (float)(NTAB - 1) / DMAX;
        float x = s_d[p] * TSCALE;
        int i0 = (int)x;
        if (i0 > NTAB - 2) i0 = NTAB - 2;
        float f = x - (float)i0;
        const float* kr = g_Ktab + ((size_t)h * NTAB + i0) * HD;
        const float* vr = g_Vtab + ((size_t)h * NTAB + i0) * HD;
        for (int c = q; c < 25; c += 4) {
            float4 a0v = *(const float4*)(kr + 4 * c);
            float4 a1v = *(const float4*)(kr + HD + 4 * c);
            float4 o;
            o.x = fmaf(f, a1v.x - a0v.x, a0v.x);
            o.y = fmaf(f, a1v.y - a0v.y, a0v.y);
            o.z = fmaf(f, a1v.z - a0v.z, a0v.z);
            o.w = fmaf(f, a1v.w - a0v.w, a0v.w);
            *(float4*)(s_h2 + p * HD + 4 * c) = o;
            float4 b0v = *(const float4*)(vr + 4 * c);
            float4 b1v = *(const float4*)(vr + HD + 4 * c);
            float4 ov;
            ov.x = fmaf(f, b1v.x - b0v.x, b0v.x);
            ov.y = fmaf(f, b1v.y - b0v.y, b0v.y);
            ov.z = fmaf(f, b1v.z - b0v.z, b0v.z);
            ov.w = fmaf(f, b1v.w - b0v.w, b0v.w);
            *(float4*)(s_hv + p * HD + 4 * c) = ov;
        }
    }
    __syncthreads();

    // key_t = H2 @ WfF; score = dot(key_t, q)/16
    {
        const int mc = tid >> 7, r7 = tid & 127, pg = r7 >> 2, q4 = r7 & 3, ig = q4 * 4;
        const int p0 = 2 * pg, p1 = p0 + 1;
        const float* h2a = s_h2 + p0 * HD + mc * 50;
        const float* h2b = s_h2 + p1 * HD + mc * 50;
        const float* wb = s_wffT + ig * WSTR + mc * 50;
        u64t accA[4] = {0ull, 0ull, 0ull, 0ull};
        u64t accB[4] = {0ull, 0ull, 0ull, 0ull};
#pragma unroll 5
        for (int u = 0; u < 25; u++) {
            u64t hA = lds64(h2a + 2 * u);
            u64t hB = lds64(h2b + 2 * u);
#pragma unroll
            for (int ii = 0; ii < 4; ii++) {
                u64t w = lds64(wb + ii * WSTR + 2 * u);
                fma2(accA[ii], hA, w);
                fma2(accB[ii], hB, w);
            }
        }
        float ka[4], kb[4];
#pragma unroll
        for (int ii = 0; ii < 4; ii++) { ka[ii] = up2sum(accA[ii]); kb[ii] = up2sum(accB[ii]); }
        if (mc == 1) {
#pragma unroll
            for (int ii = 0; ii < 4; ii++) {
                s_scr[ii * 128 + r7] = ka[ii];
                s_scr[(4 + ii) * 128 + r7] = kb[ii];
            }
        }
        __syncthreads();
        if (mc == 0) {
#pragma unroll
            for (int ii = 0; ii < 4; ii++) {
                ka[ii] += s_scr[ii * 128 + r7];
                kb[ii] += s_scr[(4 + ii) * 128 + r7];
            }
            const int aA = a0 + p0, aB = a0 + p1;
            float4 qA = *(const float4*)(g_q + ((h * Z + z) * NPT + aA) * CH + ig);
            float4 qB = *(const float4*)(g_q + ((h * Z + z) * NPT + aB) * CH + ig);
            float sA = ka[0]*qA.x + ka[1]*qA.y + ka[2]*qA.z + ka[3]*qA.w;
            float sB = kb[0]*qB.x + kb[1]*qB.y + kb[2]*qB.z + kb[3]*qB.w;
            sA += __shfl_xor_sync(0xffffffffu, sA, 1);
            sA += __shfl_xor_sync(0xffffffffu, sA, 2);
            sB += __shfl_xor_sync(0xffffffffu, sB, 1);
            sB += __shfl_xor_sync(0xffffffffu, sB, 2);
            if (q4 == 0) {
                g_scores[((h * Z + z) * NPT + aA) * NPT + b] = sA * (1.0f / CH);
                g_scores[((h * Z + z) * NPT + aB) * NPT + b] = sB * (1.0f / CH);
            }
        }
        __syncthreads();
    }

    // val_t = Hv @ VfF
    {
        const int mc = tid >> 7, r7 = tid & 127, pg = r7 >> 2, q4 = r7 & 3, ig = q4 * 4;
        const int p0 = 2 * pg, p1 = p0 + 1;
        const float* hva = s_hv + p0 * HD + mc * 50;
        const float* hvb = s_hv + p1 * HD + mc * 50;
        const float* wb = s_vffT + ig * WSTR + mc * 50;
        u64t accA[4] = {0ull, 0ull, 0ull, 0ull};
        u64t accB[4] = {0ull, 0ull, 0ull, 0ull};
#pragma unroll 5
        for (int u = 0; u < 25; u++) {
            u64t hA = lds64(hva + 2 * u);
            u64t hB = lds64(hvb + 2 * u);
#pragma unroll
            for (int ii = 0; ii < 4; ii++) {
                u64t w = lds64(wb + ii * WSTR + 2 * u);
                fma2(accA[ii], hA, w);
                fma2(accB[ii], hB, w);
            }
        }
        float va[4], vb[4];
#pragma unroll
        for (int ii = 0; ii < 4; ii++) { va[ii] = up2sum(accA[ii]); vb[ii] = up2sum(accB[ii]); }
        float* scr = s_h2;  // dead after key contraction
        if (mc == 1) {
#pragma unroll
            for (int ii = 0; ii < 4; ii++) {
                scr[ii * 128 + r7] = va[ii];
                scr[(4 + ii) * 128 + r7] = vb[ii];
            }
        }
        __syncthreads();
        if (mc == 0) {
#pragma unroll
            for (int ii = 0; ii < 4; ii++) {
                va[ii] += scr[ii * 128 + r7];
                vb[ii] += scr[(4 + ii) * 128 + r7];
            }
            const int aA = a0 + p0, aB = a0 + p1;
            size_t baseA = ((size_t)((h * Z + z) * NPT + aA) * NPT + b) * CH + ig;
            size_t baseB = ((size_t)((h * Z + z) * NPT + aB) * NPT + b) * CH + ig;
            *(float4*)(g_valt + baseA) = make_float4(va[0], va[1], va[2], va[3]);
            *(float4*)(g_valt + baseB) = make_float4(vb[0], vb[1], vb[2], vb[3]);
        }
    }
}

// ---------------- Kernel S: softmax + weighted sum ----------------
__global__ __launch_bounds__(256) void softmax_kernel() {
    const int bid = blockIdx.x;
    const int z = bid / NPT, a = bid % NPT;
    const int tid = threadIdx.x;
    const int wid = tid >> 5, lane = tid & 31;
    __shared__ float swr[8];
    __shared__ float vr[8 * CH];

    float accv[CH];
#pragma unroll
    for (int i = 0; i < CH; i++) accv[i] = 0.f;

#pragma unroll
    for (int h = 0; h < HEADS; h++) {
        float sc = g_scores[((h * Z + z) * NPT + a) * NPT + tid];
        float m = sc;
#pragma unroll
        for (int s = 16; s > 0; s >>= 1) m = fmaxf(m, __shfl_xor_sync(0xffffffffu, m, s));
        if (lane == 0) swr[wid] = m;
        __syncthreads();
        float mx = swr[0];
#pragma unroll
        for (int j = 1; j < 8; j++) mx = fmaxf(mx, swr[j]);
        __syncthreads();
        float e = __expf(sc - mx);
        float sum = e;
#pragma unroll
        for (int s = 16; s > 0; s >>= 1) sum += __shfl_xor_sync(0xffffffffu, sum, s);
        if (lane == 0) swr[wid] = sum;
        __syncthreads();
        float tot = swr[0];
#pragma unroll
        for (int j = 1; j < 8; j++) tot += swr[j];
        __syncthreads();
        float p = e / tot;

        const float4* vp = (const float4*)(g_valt +
            ((size_t)((h * Z + z) * NPT + a) * NPT + tid) * CH);
#pragma unroll
        for (int k = 0; k < 4; k++) {
            float4 v = vp[k];
            accv[k * 4 + 0] += p * v.x;
            accv[k * 4 + 1] += p * v.y;
            accv[k * 4 + 2] += p * v.z;
            accv[k * 4 + 3] += p * v.w;
        }
    }
#pragma unroll
    for (int s = 16; s > 0; s >>= 1)
#pragma unroll
        for (int i = 0; i < CH; i++) accv[i] += __shfl_xor_sync(0xffffffffu, accv[i], s);
    if (lane == 0)
#pragma unroll
        for (int i = 0; i < CH; i++) vr[wid * CH + i] = accv[i];
    __syncthreads();
    if (tid < CH) {
        float acc = 0.f;
#pragma unroll
        for (int w = 0; w < 8; w++) acc += vr[w * CH + tid];
        g_attnout[(z * NPT + a) * CH + tid] = acc;
    }
}

// ---------------- Kernel C1: CfF projection ----------------
__global__ __launch_bounds__(256) void cff_kernel(const float* __restrict__ Cf) {
    const int z = blockIdx.x >> 5;
    const int b0 = (blockIdx.x & 31) * 8;
    const int tid = threadIdx.x;
    __shared__ float ao[8 * CH];
    if (tid < 8 * CH) ao[tid] = g_attnout[(z * NPT + b0) * CH + tid];
    __syncthreads();
    for (int e = tid; e < HD * CH; e += 256) {
        const int i = e / HD, m = e - i * HD;
        const float* cp = Cf + m * (CH * CH) + i * CH;
        float4 c0 = *(const float4*)(cp);
        float4 c1 = *(const float4*)(cp + 4);
        float4 c2 = *(const float4*)(cp + 8);
        float4 c3 = *(const float4*)(cp + 12);
#pragma unroll
        for (int bl = 0; bl < 8; bl++) {
            const float* f = ao + bl * CH;
            float acc = c0.x*f[0]+c0.y*f[1]+c0.z*f[2]+c0.w*f[3]
                      + c1.x*f[4]+c1.y*f[5]+c1.z*f[6]+c1.w*f[7]
                      + c2.x*f[8]+c2.y*f[9]+c2.z*f[10]+c2.w*f[11]
                      + c3.x*f[12]+c3.y*f[13]+c3.z*f[14]+c3.w*f[15];
            g_CfF[(z * NPT + b0 + bl) * (HD * CH) + e] = acc;
        }
    }
}

// ---------------- Kernel C2: final conv (table-based) ----------------
__global__ __launch_bounds__(256) void conv_kernel(const float* __restrict__ xyz,
                                                   float* __restrict__ out) {
    __shared__ float smc[9120];
    float* s_cffT = smc;            // 1632
    float* s_h2   = smc + 1632;     // 6400
    float* s_d    = smc + 8032;     // 64
    float* s_scr  = smc + 8096;     // 1024

    const int tid = threadIdx.x;
    const int b = blockIdx.x;
    const int a0 = blockIdx.y * ATILE;
    const int z = blockIdx.z;

    {
        const int base = (z * NPT + b) * (HD * CH);
        for (int e = tid; e < HD * CH; e += 256) {
            int i = e / HD, m = e - i * HD;
            s_cffT[i * WSTR + m] = g_CfF[base + e];
        }
    }
    if (tid < ATILE) {
        int a = a0 + tid;
        float bx = xyz[(z * NPT + b) * 3 + 0];
        float by = xyz[(z * NPT + b) * 3 + 1];
        float bz = xyz[(z * NPT + b) * 3 + 2];
        float dx = bx - xyz[(z * NPT + a) * 3 + 0];
        float dy = by - xyz[(z * NPT + a) * 3 + 1];
        float dz = bz - xyz[(z * NPT + a) * 3 + 2];
        s_d[tid] = sqrtf(dx * dx + dy * dy + dz * dz + 1e-12f);
    }
    __syncthreads();

    {
        const int p = tid >> 2, q = tid & 3;
        const float TSCALE = (float)(NTAB - 1) / DMAX;
        float x = s_d[p] * TSCALE;
        int i0 = (int)x;
        if (i0 > NTAB - 2) i0 = NTAB - 2;
        float f = x - (float)i0;
        const float* cr = g_Ctab + (size_t)i0 * HD;
        for (int c = q; c < 25; c += 4) {
            float4 a0v = *(const float4*)(cr + 4 * c);
            float4 a1v = *(const float4*)(cr + HD + 4 * c);
            float4 o;
            o.x = fmaf(f, a1v.x - a0v.x, a0v.x);
            o.y = fmaf(f, a1v.y - a0v.y, a0v.y);
            o.z = fmaf(f, a1v.z - a0v.z, a0v.z);
            o.w = fmaf(f, a1v.w - a0v.w, a0v.w);
            *(float4*)(s_h2 + p * HD + 4 * c) = o;
        }
    }
    __syncthreads();

    {
        const int mc = tid >> 7, r7 = tid & 127, pg = r7 >> 2, q4 = r7 & 3, ig = q4 * 4;
        const int p0 = 2 * pg, p1 = p0 + 1;
        const float* h2a = s_h2 + p0 * HD + mc * 50;
        const float* h2b = s_h2 + p1 * HD + mc * 50;
        const float* wb = s_cffT + ig * WSTR + mc * 50;
        u64t accA[4] = {0ull, 0ull, 0ull, 0ull};
        u64t accB[4] = {0ull, 0ull, 0ull, 0ull};
#pragma unroll 5
        for (int u = 0; u < 25; u++) {
            u64t hA = lds64(h2a + 2 * u);
            u64t hB = lds64(h2b + 2 * u);
#pragma unroll
            for (int ii = 0; ii < 4; ii++) {
                u64t w = lds64(wb + ii * WSTR + 2 * u);
                fma2(accA[ii], hA, w);
                fma2(accB[ii], hB, w);
            }
        }
        float va[4], vb[4];
#pragma unroll
        for (int ii = 0; ii < 4; ii++) { va[ii] = up2sum(accA[ii]); vb[ii] = up2sum(accB[ii]); }
        if (mc == 1) {
#pragma unroll
            for (int ii = 0; ii < 4; ii++) {
                s_scr[ii * 128 + r7] = va[ii];
                s_scr[(4 + ii) * 128 + r7] = vb[ii];
            }
        }
        __syncthreads();
        if (mc == 0) {
            const int aA = a0 + p0, aB = a0 + p1;
            float* opA = out + (z * NPT + aA) * CH + ig;
            float* opB = out + (z * NPT + aB) * CH + ig;
#pragma unroll
            for (int ii = 0; ii < 4; ii++) {
                atomicAdd(opA + ii, va[ii] + s_scr[ii * 128 + r7]);
                atomicAdd(opB + ii, vb[ii] + s_scr[(4 + ii) * 128 + r7]);
            }
        }
    }
}

// ---------------- launch ----------------
extern "C" void kernel_launch(void* const* d_in, const int* in_sizes, int n_in,
                              void* d_out, int out_size) {
    const float* features = (const float*)d_in[0];
    const float* xyz = (const float*)d_in[1];
    const float* Wq = (const float*)d_in[2];
    const float* K0 = (const float*)d_in[3];
    const float* K1 = (const float*)d_in[4];
    const float* Kf = (const float*)d_in[5];
    const float* V0 = (const float*)d_in[6];
    const float* Vf = (const float*)d_in[7];
    const float* C0 = (const float*)d_in[8];
    const float* C1 = (const float*)d_in[9];
    const float* Cf = (const float*)d_in[10];
    float* out = (float*)d_out;

    cudaFuncSetAttribute(table2_kernel, cudaFuncAttributeMaxDynamicSharedMemorySize,
                         T2_SMEM_FLOATS * (int)sizeof(float));
    cudaFuncSetAttribute(pair_kernel, cudaFuncAttributeMaxDynamicSharedMemorySize,
                         P_SMEM_FLOATS * (int)sizeof(float));

    cudaMemsetAsync(d_out, 0, (size_t)out_size * sizeof(float));

    transpose_weights<<<79, 256>>>(K0, K1, C0, C1);
    table2_kernel<<<dim3(NTAB / 64, 3), 256, T2_SMEM_FLOATS * sizeof(float)>>>();
    table1_kernel<<<dim3(NTAB / 64, 2), 256>>>(V0);
    proj_kernel<<<Z * 32, 256>>>(features, Wq, Kf, Vf);
    pair_kernel<<<dim3(NPT, NPT / ATILE, Z * HEADS), 256,
                  P_SMEM_FLOATS * sizeof(float)>>>(xyz);
    softmax_kernel<<<Z * NPT, 256>>>();
    cff_kernel<<<Z * 32, 256>>>(Cf);
    conv_kernel<<<dim3(NPT, NPT / ATILE, Z), 256>>>(xyz, out);
}

// round 5
// speedup vs baseline: 3.8390x; 1.2677x over previous
#include <cuda_runtime.h>
#include <math.h>

#define Z 2
#define NPT 256
#define CH 16
#define HEADS 2
#define NB 10
#define HD 100
#define NBV 3
#define K1STR 102
#define WSTR 102
#define NTAB 4096
#define DMAX 8.7f
#define STEP10 (5.0f / 9.0f)
#define INV10 (9.0f / 5.0f)

typedef unsigned long long u64t;

// ---------------- scratch ----------------
__device__ float g_q[HEADS * Z * NPT * CH];
__device__ float g_WfF[HEADS * Z * NPT * HD * CH];   // [h][z][b][i][m]
__device__ float g_VfF[HEADS * Z * NPT * HD * CH];
__device__ float g_CfF[Z * NPT * HD * CH];
__device__ float g_scores[HEADS * Z * NPT * NPT];
__device__ float g_valt[HEADS * Z * NPT * NPT * CH];
__device__ float g_attnout[Z * NPT * CH];
__device__ float g_K0T[HEADS * HD * NB];
__device__ float g_K1T[HEADS * HD * HD];
__device__ float g_C0T[HD * NB];
__device__ float g_C1T[HD * HD];
__device__ float g_Ktab[HEADS * NTAB * HD];
__device__ float g_Ctab[NTAB * HD];
__device__ float g_Vtab[HEADS * NTAB * HD];

__device__ __forceinline__ float swishf(float x) {
    return x / (1.0f + __expf(-x));
}
__device__ __forceinline__ void fma2(u64t& d, u64t a, u64t b) {
    asm("fma.rn.f32x2 %0, %1, %2, %0;" : "+l"(d) : "l"(a), "l"(b));
}
__device__ __forceinline__ float up2sum(u64t v) {
    float2 f;
    asm("mov.b64 {%0, %1}, %2;" : "=f"(f.x), "=f"(f.y) : "l"(v));
    return f.x + f.y;
}
__device__ __forceinline__ u64t lds64(const float* p) {
    return *(const u64t*)p;
}

// ---------------- Kernel 1: transposes + value tables (fused, independent parts) ----------------
__global__ __launch_bounds__(256) void prep_kernel(const float* __restrict__ K0,
                                                   const float* __restrict__ K1,
                                                   const float* __restrict__ C0,
                                                   const float* __restrict__ C1,
                                                   const float* __restrict__ V0) {
    const int bx = blockIdx.x;
    const int tid = threadIdx.x;
    if (bx < 79) {
        int idx = bx * 256 + tid;
        if (idx < 2000) {
            int h = idx / 1000, r = idx % 1000, m = r / NB, n = r % NB;
            g_K0T[idx] = K0[h * NB * HD + n * HD + m];
        }
        if (idx < 20000) {
            int h = idx / 10000, r = idx % 10000, m = r / HD, n = r % HD;
            g_K1T[idx] = K1[h * HD * HD + n * HD + m];
        }
        if (idx < 1000) {
            int m = idx / NB, n = idx % NB;
            g_C0T[idx] = C0[n * HD + m];
        }
        if (idx < 10000) {
            int m = idx / HD, n = idx % HD;
            g_C1T[idx] = C1[n * HD + m];
        }
    } else {
        // value radial tables
        int t = bx - 79;               // 0..127
        int h = t >> 6;
        int p0 = (t & 63) * 64;
        const int p = tid >> 2, q = tid & 3;
        const float DELTA = DMAX / (float)(NTAB - 1);
        float d = (float)(p0 + p) * DELTA;
        float bas[NBV];
#pragma unroll
        for (int n = 0; n < NBV; n++) {
            float diff = (d - n * 2.5f) * 0.4f;
            bas[n] = (fabsf(diff) < 1.0f) ? cospif(0.5f * diff) : 0.0f;
        }
        const float* v = V0 + h * NBV * HD;
        float* row = g_Vtab + (size_t)h * NTAB * HD + (size_t)(p0 + p) * HD;
#pragma unroll 5
        for (int u = 0; u < 25; u++) {
            int m = q * 25 + u;
            float acc = bas[0] * v[m] + bas[1] * v[HD + m] + bas[2] * v[2 * HD + m];
            row[m] = swishf(acc);
        }
    }
}

// ---------------- Kernel 2: radial2 tables + projections (fused) ----------------
#define B_SMEM_FLOATS 18240
__global__ __launch_bounds__(256) void build_kernel(const float* __restrict__ features,
                                                    const float* __restrict__ Wq,
                                                    const float* __restrict__ Kf,
                                                    const float* __restrict__ Vf) {
    extern __shared__ float sm[];
    const int bx = blockIdx.x;
    const int tid = threadIdx.x;

    if (bx < 192) {
        // --- table2: 3 nets x 64 blocks of 64 d-points ---
        float* s_k0T = sm;            // 1000
        float* s_k1T = sm + 1000;     // 10200
        float* s_bas = sm + 11200;    // 640
        float* s_h1  = sm + 11840;    // 6400
        const int net = bx / 64;
        const int p0 = (bx % 64) * 64;
        const float* K0src = (net < 2) ? (g_K0T + net * HD * NB) : g_C0T;
        const float* K1src = (net < 2) ? (g_K1T + net * HD * HD) : g_C1T;
        float* tab = (net < 2) ? (g_Ktab + (size_t)net * NTAB * HD) : g_Ctab;

        for (int i = tid; i < HD * NB; i += 256) s_k0T[i] = K0src[i];
        for (int e = tid; e < HD * HD; e += 256) {
            int m = e / HD, n = e - m * HD;
            s_k1T[m * K1STR + n] = K1src[e];
        }
        const float DELTA = DMAX / (float)(NTAB - 1);
        for (int e = tid; e < 64 * NB; e += 256) {
            int p = e / NB, n = e - p * NB;
            float d = (float)(p0 + p) * DELTA;
            float diff = (d - n * STEP10) * INV10;
            s_bas[e] = (fabsf(diff) < 1.0f) ? cospif(0.5f * diff) : 0.0f;
        }
        __syncthreads();

        {
            const int p = tid >> 2, q4 = tid & 3;
            const float* bp = s_bas + p * NB;
            u64t bb0 = lds64(bp), bb1 = lds64(bp + 2), bb2 = lds64(bp + 4),
                 bb3 = lds64(bp + 6), bb4 = lds64(bp + 8);
#pragma unroll 5
            for (int mm = 0; mm < 25; mm++) {
                int m = q4 * 25 + mm;
                const float* kp = s_k0T + m * NB;
                u64t acc = 0ull;
                fma2(acc, bb0, lds64(kp));
                fma2(acc, bb1, lds64(kp + 2));
                fma2(acc, bb2, lds64(kp + 4));
                fma2(acc, bb3, lds64(kp + 6));
                fma2(acc, bb4, lds64(kp + 8));
                s_h1[p * HD + m] = swishf(up2sum(acc));
            }
        }
        __syncthreads();

        {
            const int ty = tid >> 4, tx = tid & 15;
            const float* hbase = s_h1 + ty * 4 * HD;
            const bool tail = tx < 4;
            u64t acc[4][7];
#pragma unroll
            for (int r = 0; r < 4; r++)
#pragma unroll
                for (int j = 0; j < 7; j++) acc[r][j] = 0ull;
#pragma unroll 2
            for (int t = 0; t < 50; t++) {
                u64t h0 = lds64(hbase + 2 * t);
                u64t h1v = lds64(hbase + HD + 2 * t);
                u64t h2v = lds64(hbase + 2 * HD + 2 * t);
                u64t h3v = lds64(hbase + 3 * HD + 2 * t);
#pragma unroll
                for (int j = 0; j < 6; j++) {
                    u64t kv = lds64(s_k1T + (tx + 16 * j) * K1STR + 2 * t);
                    fma2(acc[0][j], h0, kv);
                    fma2(acc[1][j], h1v, kv);
                    fma2(acc[2][j], h2v, kv);
                    fma2(acc[3][j], h3v, kv);
                }
                if (tail) {
                    u64t kv = lds64(s_k1T + (tx + 96) * K1STR + 2 * t);
                    fma2(acc[0][6], h0, kv);
                    fma2(acc[1][6], h1v, kv);
                    fma2(acc[2][6], h2v, kv);
                    fma2(acc[3][6], h3v, kv);
                }
            }
#pragma unroll
            for (int r = 0; r < 4; r++) {
                float* row = tab + (size_t)(p0 + ty * 4 + r) * HD;
#pragma unroll
                for (int j = 0; j < 6; j++)
                    row[tx + 16 * j] = swishf(up2sum(acc[r][j]));
                if (tail)
                    row[tx + 96] = swishf(up2sum(acc[r][6]));
            }
        }
    } else {
        // --- proj: 256 blocks = 64 (z,b-groups) x 4 m-slices ---
        float* fs = sm;  // 128
        const int t = bx - 192;
        const int zb = t >> 2;
        const int z = zb >> 5;
        const int b0 = (zb & 31) * 8;
        const int sl = t & 3;
        if (tid < 8 * CH) fs[tid] = features[(z * NPT + b0) * CH + tid];
        __syncthreads();

        if (sl == 0) {
            const int bl = tid >> 5, r = tid & 31, h = r >> 4, o = r & 15;
            float acc = 0.f;
#pragma unroll
            for (int i = 0; i < CH; i++) acc += fs[bl * CH + i] * Wq[(h * CH + o) * CH + i];
            g_q[((h * Z + z) * NPT + b0 + bl) * CH + o] = acc;
        }

        for (int e = tid; e < HEADS * 25 * CH; e += 256) {
            const int h = e / 400;
            const int rr = e - h * 400;
            const int i = rr / 25, mm = rr - i * 25;
            const int m = sl * 25 + mm;
            const int r = i * HD + m;
            const float* kfp = Kf + (h * HD + m) * (CH * CH) + i * CH;
            const float* vfp = Vf + (h * HD + m) * (CH * CH) + i * CH;
            float4 k0 = *(const float4*)(kfp);
            float4 k1 = *(const float4*)(kfp + 4);
            float4 k2 = *(const float4*)(kfp + 8);
            float4 k3 = *(const float4*)(kfp + 12);
            float4 v0 = *(const float4*)(vfp);
            float4 v1 = *(const float4*)(vfp + 4);
            float4 v2 = *(const float4*)(vfp + 8);
            float4 v3 = *(const float4*)(vfp + 12);
#pragma unroll
            for (int bl = 0; bl < 8; bl++) {
                const float* f = fs + bl * CH;
                float aK = k0.x*f[0]+k0.y*f[1]+k0.z*f[2]+k0.w*f[3]
                         + k1.x*f[4]+k1.y*f[5]+k1.z*f[6]+k1.w*f[7]
                         + k2.x*f[8]+k2.y*f[9]+k2.z*f[10]+k2.w*f[11]
                         + k3.x*f[12]+k3.y*f[13]+k3.z*f[14]+k3.w*f[15];
                float aV = v0.x*f[0]+v0.y*f[1]+v0.z*f[2]+v0.w*f[3]
                         + v1.x*f[4]+v1.y*f[5]+v1.z*f[6]+v1.w*f[7]
                         + v2.x*f[8]+v2.y*f[9]+v2.z*f[10]+v2.w*f[11]
                         + v3.x*f[12]+v3.y*f[13]+v3.z*f[14]+v3.w*f[15];
                int o = ((h * Z + z) * NPT + b0 + bl) * (HD * CH) + r;
                g_WfF[o] = aK;
                g_VfF[o] = aV;
            }
        }
    }
}

// ---------------- Kernel P: pair kernel (per-b persistent, 4 a-chunks) ----------------
#define P_SMEM_FLOATS 16320
__global__ __launch_bounds__(256) void pair_kernel(const float* __restrict__ xyz) {
    extern __shared__ float sm[];
    float* s_wffT = sm;            // 1632  [i][102]
    float* s_vffT = sm + 1632;     // 1632
    float* s_h2   = sm + 3264;     // 6400  [p][100]
    float* s_hv   = sm + 9664;     // 6400
    float* s_d    = sm + 16064;    // 256

    const int tid = threadIdx.x;
    const int b = blockIdx.x;
    const int z = blockIdx.y >> 1;
    const int h = blockIdx.y & 1;

    {
        const int base = ((h * Z + z) * NPT + b) * (HD * CH);
        for (int e = tid; e < HD * CH; e += 256) {
            int i = e / HD, m = e - i * HD;
            s_wffT[i * WSTR + m] = g_WfF[base + e];
            s_vffT[i * WSTR + m] = g_VfF[base + e];
        }
    }
    {
        float bx = xyz[(z * NPT + b) * 3 + 0];
        float by = xyz[(z * NPT + b) * 3 + 1];
        float bz = xyz[(z * NPT + b) * 3 + 2];
        float dx = bx - xyz[(z * NPT + tid) * 3 + 0];
        float dy = by - xyz[(z * NPT + tid) * 3 + 1];
        float dz = bz - xyz[(z * NPT + tid) * 3 + 2];
        s_d[tid] = sqrtf(dx * dx + dy * dy + dz * dz + 1e-12f);
    }
    __syncthreads();

    // contraction thread mapping
    const int kv = tid >> 7;              // 0=key, 1=val
    const int r7 = tid & 127;
    const int pg = r7 >> 3;               // 16 groups of 4 p
    const int q4 = (r7 >> 1) & 3;         // 4 i-groups
    const int mc = r7 & 1;                // m half
    const int pb = pg * 4;
    const int ig = q4 * 4;
    const float* hsrc = (kv ? s_hv : s_h2) + pb * HD + mc * 50;
    const float* wsrc = (kv ? s_vffT : s_wffT) + ig * WSTR + mc * 50;

    for (int ch = 0; ch < 4; ch++) {
        const int ach0 = ch * 64;
        // gather + lerp
        {
            const int p = tid >> 2, q = tid & 3;
            const float TSCALE = (float)(NTAB - 1) / DMAX;
            float x = s_d[ach0 + p] * TSCALE;
            int i0 = (int)x;
            if (i0 > NTAB - 2) i0 = NTAB - 2;
            float f = x - (float)i0;
            const float* kr = g_Ktab + ((size_t)h * NTAB + i0) * HD;
            const float* vr = g_Vtab + ((size_t)h * NTAB + i0) * HD;
            for (int c = q; c < 25; c += 4) {
                float4 a0v = *(const float4*)(kr + 4 * c);
                float4 a1v = *(const float4*)(kr + HD + 4 * c);
                float4 o;
                o.x = fmaf(f, a1v.x - a0v.x, a0v.x);
                o.y = fmaf(f, a1v.y - a0v.y, a0v.y);
                o.z = fmaf(f, a1v.z - a0v.z, a0v.z);
                o.w = fmaf(f, a1v.w - a0v.w, a0v.w);
                *(float4*)(s_h2 + p * HD + 4 * c) = o;
                float4 b0v = *(const float4*)(vr + 4 * c);
                float4 b1v = *(const float4*)(vr + HD + 4 * c);
                float4 ov;
                ov.x = fmaf(f, b1v.x - b0v.x, b0v.x);
                ov.y = fmaf(f, b1v.y - b0v.y, b0v.y);
                ov.z = fmaf(f, b1v.z - b0v.z, b0v.z);
                ov.w = fmaf(f, b1v.w - b0v.w, b0v.w);
                *(float4*)(s_hv + p * HD + 4 * c) = ov;
            }
        }
        __syncthreads();

        // contraction: 4p x 4i, m-split 2, key/val in block halves
        {
            u64t acc[4][4];
#pragma unroll
            for (int r = 0; r < 4; r++)
#pragma unroll
                for (int ii = 0; ii < 4; ii++) acc[r][ii] = 0ull;
#pragma unroll 5
            for (int u = 0; u < 25; u++) {
                u64t h0 = lds64(hsrc + 2 * u);
                u64t h1 = lds64(hsrc + HD + 2 * u);
                u64t h2 = lds64(hsrc + 2 * HD + 2 * u);
                u64t h3 = lds64(hsrc + 3 * HD + 2 * u);
#pragma unroll
                for (int ii = 0; ii < 4; ii++) {
                    u64t w = lds64(wsrc + ii * WSTR + 2 * u);
                    fma2(acc[0][ii], h0, w);
                    fma2(acc[1][ii], h1, w);
                    fma2(acc[2][ii], h2, w);
                    fma2(acc[3][ii], h3, w);
                }
            }
            float s[4][4];
#pragma unroll
            for (int r = 0; r < 4; r++)
#pragma unroll
                for (int ii = 0; ii < 4; ii++) {
                    s[r][ii] = up2sum(acc[r][ii]);
                    s[r][ii] += __shfl_xor_sync(0xffffffffu, s[r][ii], 1);
                }

            if (kv == 0) {
                float sc[4];
#pragma unroll
                for (int r = 0; r < 4; r++) {
                    const int a = ach0 + pb + r;
                    float4 qv = *(const float4*)(g_q + ((h * Z + z) * NPT + a) * CH + ig);
                    sc[r] = s[r][0]*qv.x + s[r][1]*qv.y + s[r][2]*qv.z + s[r][3]*qv.w;
                    sc[r] += __shfl_xor_sync(0xffffffffu, sc[r], 2);
                    sc[r] += __shfl_xor_sync(0xffffffffu, sc[r], 4);
                }
                if ((r7 & 7) == 0) {
#pragma unroll
                    for (int r = 0; r < 4; r++) {
                        const int a = ach0 + pb + r;
                        g_scores[((h * Z + z) * NPT + a) * NPT + b] = sc[r] * (1.0f / CH);
                    }
                }
            } else {
                if (mc == 0) {
#pragma unroll
                    for (int r = 0; r < 4; r++) {
                        const int a = ach0 + pb + r;
                        size_t base = ((size_t)((h * Z + z) * NPT + a) * NPT + b) * CH + ig;
                        *(float4*)(g_valt + base) = make_float4(s[r][0], s[r][1], s[r][2], s[r][3]);
                    }
                }
            }
        }
        __syncthreads();
    }
}

// ---------------- Kernel S: softmax + weighted sum ----------------
__global__ __launch_bounds__(256) void softmax_kernel() {
    const int bid = blockIdx.x;
    const int z = bid / NPT, a = bid % NPT;
    const int tid = threadIdx.x;
    const int wid = tid >> 5, lane = tid & 31;
    __shared__ float swr[8];
    __shared__ float vr[8 * CH];

    float accv[CH];
#pragma unroll
    for (int i = 0; i < CH; i++) accv[i] = 0.f;

#pragma unroll
    for (int h = 0; h < HEADS; h++) {
        float sc = g_scores[((h * Z + z) * NPT + a) * NPT + tid];
        float m = sc;
#pragma unroll
        for (int s = 16; s > 0; s >>= 1) m = fmaxf(m, __shfl_xor_sync(0xffffffffu, m, s));
        if (lane == 0) swr[wid] = m;
        __syncthreads();
        float mx = swr[0];
#pragma unroll
        for (int j = 1; j < 8; j++) mx = fmaxf(mx, swr[j]);
        __syncthreads();
        float e = __expf(sc - mx);
        float sum = e;
#pragma unroll
        for (int s = 16; s > 0; s >>= 1) sum += __shfl_xor_sync(0xffffffffu, sum, s);
        if (lane == 0) swr[wid] = sum;
        __syncthreads();
        float tot = swr[0];
#pragma unroll
        for (int j = 1; j < 8; j++) tot += swr[j];
        __syncthreads();
        float p = e / tot;

        const float4* vp = (const float4*)(g_valt +
            ((size_t)((h * Z + z) * NPT + a) * NPT + tid) * CH);
#pragma unroll
        for (int k = 0; k < 4; k++) {
            float4 v = vp[k];
            accv[k * 4 + 0] += p * v.x;
            accv[k * 4 + 1] += p * v.y;
            accv[k * 4 + 2] += p * v.z;
            accv[k * 4 + 3] += p * v.w;
        }
    }
#pragma unroll
    for (int s = 16; s > 0; s >>= 1)
#pragma unroll
        for (int i = 0; i < CH; i++) accv[i] += __shfl_xor_sync(0xffffffffu, accv[i], s);
    if (lane == 0)
#pragma unroll
        for (int i = 0; i < CH; i++) vr[wid * CH + i] = accv[i];
    __syncthreads();
    if (tid < CH) {
        float acc = 0.f;
#pragma unroll
        for (int w = 0; w < 8; w++) acc += vr[w * CH + tid];
        g_attnout[(z * NPT + a) * CH + tid] = acc;
    }
}

// ---------------- Kernel C1: CfF projection (m-sliced) ----------------
__global__ __launch_bounds__(256) void cff_kernel(const float* __restrict__ Cf) {
    const int bx = blockIdx.x;
    const int z = bx >> 7;
    const int b0 = ((bx >> 2) & 31) * 8;
    const int sl = bx & 3;
    const int tid = threadIdx.x;
    __shared__ float ao[8 * CH];
    if (tid < 8 * CH) ao[tid] = g_attnout[(z * NPT + b0) * CH + tid];
    __syncthreads();
    for (int e = tid; e < 25 * CH; e += 256) {
        const int i = e / 25, mm = e - i * 25;
        const int m = sl * 25 + mm;
        const int r = i * HD + m;
        const float* cp = Cf + m * (CH * CH) + i * CH;
        float4 c0 = *(const float4*)(cp);
        float4 c1 = *(const float4*)(cp + 4);
        float4 c2 = *(const float4*)(cp + 8);
        float4 c3 = *(const float4*)(cp + 12);
#pragma unroll
        for (int bl = 0; bl < 8; bl++) {
            const float* f = ao + bl * CH;
            float acc = c0.x*f[0]+c0.y*f[1]+c0.z*f[2]+c0.w*f[3]
                      + c1.x*f[4]+c1.y*f[5]+c1.z*f[6]+c1.w*f[7]
                      + c2.x*f[8]+c2.y*f[9]+c2.z*f[10]+c2.w*f[11]
                      + c3.x*f[12]+c3.y*f[13]+c3.z*f[14]+c3.w*f[15];
            g_CfF[(z * NPT + b0 + bl) * (HD * CH) + r] = acc;
        }
    }
}

// ---------------- Kernel C2: final conv (per-b persistent) ----------------
__global__ __launch_bounds__(256) void conv_kernel(const float* __restrict__ xyz,
                                                   float* __restrict__ out) {
    __shared__ float smc[8288];
    float* s_cffT = smc;            // 1632
    float* s_h2   = smc + 1632;     // 6400
    float* s_d    = smc + 8032;     // 256

    const int tid = threadIdx.x;
    const int b = blockIdx.x;
    const int z = blockIdx.y;

    {
        const int base = (z * NPT + b) * (HD * CH);
        for (int e = tid; e < HD * CH; e += 256) {
            int i = e / HD, m = e - i * HD;
            s_cffT[i * WSTR + m] = g_CfF[base + e];
        }
    }
    {
        float bx = xyz[(z * NPT + b) * 3 + 0];
        float by = xyz[(z * NPT + b) * 3 + 1];
        float bz = xyz[(z * NPT + b) * 3 + 2];
        float dx = bx - xyz[(z * NPT + tid) * 3 + 0];
        float dy = by - xyz[(z * NPT + tid) * 3 + 1];
        float dz = bz - xyz[(z * NPT + tid) * 3 + 2];
        s_d[tid] = sqrtf(dx * dx + dy * dy + dz * dz + 1e-12f);
    }
    __syncthreads();

    const int pg = tid >> 4;              // 16 groups of 4 p
    const int q4 = (tid >> 2) & 3;        // 4 i-groups
    const int mc = tid & 3;               // m quarter
    const int pb = pg * 4;
    const int ig = q4 * 4;
    const int mstart = mc * 26;
    const int npairs = (mc < 3) ? 13 : 11;
    const float* hsrc0 = s_h2 + pb * HD + mstart;
    const float* wsrc = s_cffT + ig * WSTR + mstart;

    for (int ch = 0; ch < 4; ch++) {
        const int ach0 = ch * 64;
        {
            const int p = tid >> 2, q = tid & 3;
            const float TSCALE = (float)(NTAB - 1) / DMAX;
            float x = s_d[ach0 + p] * TSCALE;
            int i0 = (int)x;
            if (i0 > NTAB - 2) i0 = NTAB - 2;
            float f = x - (float)i0;
            const float* cr = g_Ctab + (size_t)i0 * HD;
            for (int c = q; c < 25; c += 4) {
                float4 a0v = *(const float4*)(cr + 4 * c);
                float4 a1v = *(const float4*)(cr + HD + 4 * c);
                float4 o;
                o.x = fmaf(f, a1v.x - a0v.x, a0v.x);
                o.y = fmaf(f, a1v.y - a0v.y, a0v.y);
                o.z = fmaf(f, a1v.z - a0v.z, a0v.z);
                o.w = fmaf(f, a1v.w - a0v.w, a0v.w);
                *(float4*)(s_h2 + p * HD + 4 * c) = o;
            }
        }
        __syncthreads();

        {
            u64t acc[4][4];
#pragma unroll
            for (int r = 0; r < 4; r++)
#pragma unroll
                for (int ii = 0; ii < 4; ii++) acc[r][ii] = 0ull;
            for (int u = 0; u < npairs; u++) {
                u64t h0 = lds64(hsrc0 + 2 * u);
                u64t h1 = lds64(hsrc0 + HD + 2 * u);
                u64t h2 = lds64(hsrc0 + 2 * HD + 2 * u);
                u64t h3 = lds64(hsrc0 + 3 * HD + 2 * u);
#pragma unroll
                for (int ii = 0; ii < 4; ii++) {
                    u64t w = lds64(wsrc + ii * WSTR + 2 * u);
                    fma2(acc[0][ii], h0, w);
                    fma2(acc[1][ii], h1, w);
                    fma2(acc[2][ii], h2, w);
                    fma2(acc[3][ii], h3, w);
                }
            }
            float s[4][4];
#pragma unroll
            for (int r = 0; r < 4; r++)
#pragma unroll
                for (int ii = 0; ii < 4; ii++) {
                    s[r][ii] = up2sum(acc[r][ii]);
                    s[r][ii] += __shfl_xor_sync(0xffffffffu, s[r][ii], 1);
                    s[r][ii] += __shfl_xor_sync(0xffffffffu, s[r][ii], 2);
                }
            if (mc == 0) {
#pragma unroll
                for (int r = 0; r < 4; r++) {
                    const int a = ach0 + pb + r;
                    float* op = out + (z * NPT + a) * CH + ig;
#pragma unroll
                    for (int ii = 0; ii < 4; ii++)
                        atomicAdd(op + ii, s[r][ii]);
                }
            }
        }
        __syncthreads();
    }
}

// ---------------- launch ----------------
extern "C" void kernel_launch(void* const* d_in, const int* in_sizes, int n_in,
                              void* d_out, int out_size) {
    const float* features = (const float*)d_in[0];
    const float* xyz = (const float*)d_in[1];
    const float* Wq = (const float*)d_in[2];
    const float* K0 = (const float*)d_in[3];
    const float* K1 = (const float*)d_in[4];
    const float* Kf = (const float*)d_in[5];
    const float* V0 = (const float*)d_in[6];
    const float* Vf = (const float*)d_in[7];
    const float* C0 = (const float*)d_in[8];
    const float* C1 = (const float*)d_in[9];
    const float* Cf = (const float*)d_in[10];
    float* out = (float*)d_out;

    cudaFuncSetAttribute(build_kernel, cudaFuncAttributeMaxDynamicSharedMemorySize,
                         B_SMEM_FLOATS * (int)sizeof(float));
    cudaFuncSetAttribute(pair_kernel, cudaFuncAttributeMaxDynamicSharedMemorySize,
                         P_SMEM_FLOATS * (int)sizeof(float));

    cudaMemsetAsync(d_out, 0, (size_t)out_size * sizeof(float));

    prep_kernel<<<207, 256>>>(K0, K1, C0, C1, V0);
    build_kernel<<<448, 256, B_SMEM_FLOATS * sizeof(float)>>>(features, Wq, Kf, Vf);
    pair_kernel<<<dim3(NPT, Z * HEADS), 256, P_SMEM_FLOATS * sizeof(float)>>>(xyz);
    softmax_kernel<<<Z * NPT, 256>>>();
    cff_kernel<<<256, 256>>>(Cf);
    conv_kernel<<<dim3(NPT, Z), 256>>>(xyz, out);
}